// round 1
// baseline (speedup 1.0000x reference)
#include <cuda_runtime.h>

#define BB     4
#define SQL    2048
#define SKL    2048
#define DMODEL 1024
#define NH     16
#define HDIM   64

// Scratch (allocation-free: __device__ globals). 4 x 32 MB = 128 MB.
__device__ float g_Q [(size_t)BB * SQL * DMODEL];
__device__ float g_K [(size_t)BB * SKL * DMODEL];
__device__ float g_V [(size_t)BB * SKL * DMODEL];
__device__ float g_AO[(size_t)BB * SQL * DMODEL];

// ---------------------------------------------------------------------------
// C[M,N] = A[M,K] @ W[N,K]^T + bias   (torch Linear: x @ W.T + b)
// BM=BN=128, BK=16, TM=TN=8, 256 threads.
// ---------------------------------------------------------------------------
__global__ __launch_bounds__(256) void gemm_nt(
    const float* __restrict__ A, const float* __restrict__ W,
    const float* __restrict__ bias, float* __restrict__ C,
    int M, int N, int K)
{
    __shared__ float As[16][132];   // padded to dodge bank conflicts
    __shared__ float Ws[16][132];

    const int bm  = blockIdx.y * 128;
    const int bn  = blockIdx.x * 128;
    const int tid = threadIdx.x;

    const int trow = (tid >> 4) << 3;   // 0..120 step 8
    const int tcol = (tid & 15) << 3;   // 0..120 step 8

    float acc[8][8];
#pragma unroll
    for (int i = 0; i < 8; i++)
#pragma unroll
        for (int j = 0; j < 8; j++) acc[i][j] = 0.f;

    const int lr = tid >> 2;            // 0..63
    const int lc = (tid & 3) << 2;      // 0,4,8,12

    for (int k0 = 0; k0 < K; k0 += 16) {
#pragma unroll
        for (int i = 0; i < 2; i++) {
            const int r = lr + i * 64;
            float4 av = *(const float4*)(A + (size_t)(bm + r) * K + k0 + lc);
            As[lc + 0][r] = av.x; As[lc + 1][r] = av.y;
            As[lc + 2][r] = av.z; As[lc + 3][r] = av.w;
            float4 wv = *(const float4*)(W + (size_t)(bn + r) * K + k0 + lc);
            Ws[lc + 0][r] = wv.x; Ws[lc + 1][r] = wv.y;
            Ws[lc + 2][r] = wv.z; Ws[lc + 3][r] = wv.w;
        }
        __syncthreads();

#pragma unroll
        for (int kk = 0; kk < 16; kk++) {
            float a[8], w[8];
#pragma unroll
            for (int i = 0; i < 8; i++) a[i] = As[kk][trow + i];
#pragma unroll
            for (int j = 0; j < 8; j++) w[j] = Ws[kk][tcol + j];
#pragma unroll
            for (int i = 0; i < 8; i++)
#pragma unroll
                for (int j = 0; j < 8; j++)
                    acc[i][j] = fmaf(a[i], w[j], acc[i][j]);
        }
        __syncthreads();
    }

#pragma unroll
    for (int i = 0; i < 8; i++) {
#pragma unroll
        for (int j = 0; j < 8; j += 4) {
            float4 o;
            o.x = acc[i][j + 0] + bias[bn + tcol + j + 0];
            o.y = acc[i][j + 1] + bias[bn + tcol + j + 1];
            o.z = acc[i][j + 2] + bias[bn + tcol + j + 2];
            o.w = acc[i][j + 3] + bias[bn + tcol + j + 3];
            *(float4*)(C + (size_t)(bm + trow + i) * N + bn + tcol + j) = o;
        }
    }
}

// ---------------------------------------------------------------------------
// Flash attention with key-padding mask.
// 1 thread = 1 q-row (q + 64 accumulators in registers).
// Block = 128 q-rows of one (b,h). K/V tiles of 64 keys staged in SMEM.
// Uniform branch skips masked keys entirely (= -inf score).
// ---------------------------------------------------------------------------
__global__ __launch_bounds__(128) void flash_attn(
    const float* __restrict__ Q, const float* __restrict__ K,
    const float* __restrict__ V, const int* __restrict__ kpm,
    float* __restrict__ O)
{
    const int b = blockIdx.z;
    const int h = blockIdx.y;
    const int qrow = blockIdx.x * 128 + threadIdx.x;

    __shared__ float Ks[64][64];
    __shared__ float Vs[64][64];
    __shared__ int   msk[64];

    const float scale = 0.125f;  // HD^-0.5, HD=64

    float q[64];
    {
        const float* qp = Q + ((size_t)b * SQL + qrow) * DMODEL + h * HDIM;
#pragma unroll
        for (int d4 = 0; d4 < 16; d4++) {
            float4 v = *(const float4*)(qp + d4 * 4);
            q[d4 * 4 + 0] = v.x * scale;   // fold scale into q
            q[d4 * 4 + 1] = v.y * scale;
            q[d4 * 4 + 2] = v.z * scale;
            q[d4 * 4 + 3] = v.w * scale;
        }
    }

    float acc[64];
#pragma unroll
    for (int d = 0; d < 64; d++) acc[d] = 0.f;
    float m = -1e30f, l = 0.f;

    for (int kt = 0; kt < SKL; kt += 64) {
        __syncthreads();
#pragma unroll
        for (int i = 0; i < 8; i++) {
            const int idx = threadIdx.x + i * 128;   // 0..1023
            const int r = idx >> 4;
            const int c = (idx & 15) << 2;
            *(float4*)&Ks[r][c] =
                *(const float4*)(K + ((size_t)b * SKL + kt + r) * DMODEL + h * HDIM + c);
            *(float4*)&Vs[r][c] =
                *(const float4*)(V + ((size_t)b * SKL + kt + r) * DMODEL + h * HDIM + c);
        }
        if (threadIdx.x < 64) msk[threadIdx.x] = kpm[b * SKL + kt + threadIdx.x];
        __syncthreads();

        for (int j = 0; j < 64; j++) {
            if (msk[j] == 0) continue;   // uniform across block: cheap skip

            float s0 = 0.f, s1 = 0.f, s2 = 0.f, s3 = 0.f;
#pragma unroll
            for (int d4 = 0; d4 < 16; d4++) {
                float4 kv = *(const float4*)&Ks[j][d4 * 4];   // SMEM broadcast
                s0 = fmaf(q[d4 * 4 + 0], kv.x, s0);
                s1 = fmaf(q[d4 * 4 + 1], kv.y, s1);
                s2 = fmaf(q[d4 * 4 + 2], kv.z, s2);
                s3 = fmaf(q[d4 * 4 + 3], kv.w, s3);
            }
            const float s = (s0 + s1) + (s2 + s3);

            if (s > m) {                 // rare (~log N times per row)
                const float corr = __expf(m - s);
                m = s;
                l *= corr;
#pragma unroll
                for (int d = 0; d < 64; d++) acc[d] *= corr;
            }
            const float p = __expf(s - m);
            l += p;
#pragma unroll
            for (int d4 = 0; d4 < 16; d4++) {
                float4 vv = *(const float4*)&Vs[j][d4 * 4];   // SMEM broadcast
                acc[d4 * 4 + 0] = fmaf(p, vv.x, acc[d4 * 4 + 0]);
                acc[d4 * 4 + 1] = fmaf(p, vv.y, acc[d4 * 4 + 1]);
                acc[d4 * 4 + 2] = fmaf(p, vv.z, acc[d4 * 4 + 2]);
                acc[d4 * 4 + 3] = fmaf(p, vv.w, acc[d4 * 4 + 3]);
            }
        }
    }

    const float inv = 1.f / l;
    float* op = O + ((size_t)b * SQL + qrow) * DMODEL + h * HDIM;
#pragma unroll
    for (int d4 = 0; d4 < 16; d4++) {
        float4 o;
        o.x = acc[d4 * 4 + 0] * inv;
        o.y = acc[d4 * 4 + 1] * inv;
        o.z = acc[d4 * 4 + 2] * inv;
        o.w = acc[d4 * 4 + 3] * inv;
        *(float4*)(op + d4 * 4) = o;
    }
}

// ---------------------------------------------------------------------------
extern "C" void kernel_launch(void* const* d_in, const int* in_sizes, int n_in,
                              void* d_out, int out_size)
{
    const float* query = (const float*)d_in[0];
    const float* key   = (const float*)d_in[1];
    const float* value = (const float*)d_in[2];
    const int*   kpm   = (const int*)  d_in[3];
    const float* Wq    = (const float*)d_in[4];
    const float* bq    = (const float*)d_in[5];
    const float* Wk    = (const float*)d_in[6];
    const float* bk    = (const float*)d_in[7];
    const float* Wv    = (const float*)d_in[8];
    const float* bv    = (const float*)d_in[9];
    const float* Wo    = (const float*)d_in[10];
    const float* bo    = (const float*)d_in[11];
    float* out = (float*)d_out;

    float *Qp, *Kp, *Vp, *AOp;
    cudaGetSymbolAddress((void**)&Qp,  g_Q);
    cudaGetSymbolAddress((void**)&Kp,  g_K);
    cudaGetSymbolAddress((void**)&Vp,  g_V);
    cudaGetSymbolAddress((void**)&AOp, g_AO);

    const int M = BB * SQL;            // 8192
    dim3 gGemm(DMODEL / 128, M / 128); // (8, 64)

    gemm_nt<<<gGemm, 256>>>(query, Wq, bq, Qp, M, DMODEL, DMODEL);
    gemm_nt<<<gGemm, 256>>>(key,   Wk, bk, Kp, BB * SKL, DMODEL, DMODEL);
    gemm_nt<<<gGemm, 256>>>(value, Wv, bv, Vp, BB * SKL, DMODEL, DMODEL);

    dim3 gAttn(SQL / 128, NH, BB);     // (16, 16, 4)
    flash_attn<<<gAttn, 128>>>(Qp, Kp, Vp, kpm, AOp);

    gemm_nt<<<gGemm, 256>>>(AOp, Wo, bo, out, M, DMODEL, DMODEL);
}

// round 3
// speedup vs baseline: 2.1064x; 2.1064x over previous
#include <cuda_runtime.h>
#include <cuda_bf16.h>
#include <cstdint>

#define BB     4
#define SQL    2048
#define SKL    2048
#define DMODEL 1024
#define NH     16
#define HDIM   64

// Scratch (allocation-free: __device__ globals). 4 x 32 MB = 128 MB.
__device__ float g_Q [(size_t)BB * SQL * DMODEL];
__device__ float g_K [(size_t)BB * SKL * DMODEL];
__device__ float g_V [(size_t)BB * SKL * DMODEL];
__device__ float g_AO[(size_t)BB * SQL * DMODEL];

// ===========================================================================
// HMMA m16n8k16 bf16 -> fp32 (supported in baseline compute_103 PTX)
// ===========================================================================
__device__ __forceinline__ void mma16816(float c[4],
                                         uint32_t a0, uint32_t a1,
                                         uint32_t a2, uint32_t a3,
                                         uint32_t b0, uint32_t b1) {
    asm volatile(
        "mma.sync.aligned.m16n8k16.row.col.f32.bf16.bf16.f32 "
        "{%0,%1,%2,%3}, {%4,%5,%6,%7}, {%8,%9}, {%0,%1,%2,%3};"
        : "+f"(c[0]), "+f"(c[1]), "+f"(c[2]), "+f"(c[3])
        : "r"(a0), "r"(a1), "r"(a2), "r"(a3), "r"(b0), "r"(b1));
}

// fp32x4 -> packed bf16 hi / lo (3-term split for ~fp32 GEMM accuracy)
__device__ __forceinline__ void split_pack4(float4 v, uint2& h, uint2& l) {
    __nv_bfloat16 hx = __float2bfloat16_rn(v.x);
    __nv_bfloat16 hy = __float2bfloat16_rn(v.y);
    __nv_bfloat16 hz = __float2bfloat16_rn(v.z);
    __nv_bfloat16 hw = __float2bfloat16_rn(v.w);
    __nv_bfloat16 lx = __float2bfloat16_rn(v.x - __bfloat162float(hx));
    __nv_bfloat16 ly = __float2bfloat16_rn(v.y - __bfloat162float(hy));
    __nv_bfloat16 lz = __float2bfloat16_rn(v.z - __bfloat162float(hz));
    __nv_bfloat16 lw = __float2bfloat16_rn(v.w - __bfloat162float(hw));
    h.x = ((uint32_t)__bfloat16_as_ushort(hy) << 16) | __bfloat16_as_ushort(hx);
    h.y = ((uint32_t)__bfloat16_as_ushort(hw) << 16) | __bfloat16_as_ushort(hz);
    l.x = ((uint32_t)__bfloat16_as_ushort(ly) << 16) | __bfloat16_as_ushort(lx);
    l.y = ((uint32_t)__bfloat16_as_ushort(lw) << 16) | __bfloat16_as_ushort(lz);
}

// ===========================================================================
// Tensor-core GEMM: C[M,1024] = A[M,1024] @ W[1024,1024]^T + bias
// CTA 128x128, BK=32, 8 warps in 2x4 -> warp tile 64x32.
// bf16 3-term split. SMEM rows padded to 40 bf16 (conflict-free frag LDS).
// ===========================================================================
#define BK      32
#define LDS_ROW 40          // bf16 elements per smem row (32 data + 8 pad)

__global__ __launch_bounds__(256) void gemm_tc(
    const float* __restrict__ A, const float* __restrict__ W,
    const float* __restrict__ bias, float* __restrict__ C)
{
    __shared__ __nv_bfloat16 sAhi[128 * LDS_ROW];
    __shared__ __nv_bfloat16 sAlo[128 * LDS_ROW];
    __shared__ __nv_bfloat16 sBhi[128 * LDS_ROW];
    __shared__ __nv_bfloat16 sBlo[128 * LDS_ROW];

    const int tid  = threadIdx.x;
    const int w    = tid >> 5;
    const int lane = tid & 31;
    const int gid  = lane >> 2;      // 0..7
    const int tig  = lane & 3;       // 0..3
    const int bm   = blockIdx.y * 128;
    const int bn   = blockIdx.x * 128;

    const int wm = (w & 1) * 64;     // warp m offset within CTA tile
    const int wn = (w >> 1) * 32;    // warp n offset

    float acc[4][4][4];              // [am][an][c0..3]
#pragma unroll
    for (int i = 0; i < 4; i++)
#pragma unroll
        for (int j = 0; j < 4; j++)
#pragma unroll
            for (int k = 0; k < 4; k++) acc[i][j][k] = 0.f;

    // GMEM staging: thread t loads row t>>1, cols (t&1)*16 .. +15 (4 float4)
    const int lrow = tid >> 1;
    const int lcol = (tid & 1) * 16;

    for (int k0 = 0; k0 < 1024; k0 += BK) {
        __syncthreads();   // previous stage's frags consumed
        {
            const float* ap = A + (size_t)(bm + lrow) * 1024 + k0 + lcol;
            const float* bp = W + (size_t)(bn + lrow) * 1024 + k0 + lcol;
#pragma unroll
            for (int c4 = 0; c4 < 4; c4++) {
                uint2 h, l;
                float4 av = *(const float4*)(ap + c4 * 4);
                split_pack4(av, h, l);
                *(uint2*)&sAhi[lrow * LDS_ROW + lcol + c4 * 4] = h;
                *(uint2*)&sAlo[lrow * LDS_ROW + lcol + c4 * 4] = l;
                float4 bv = *(const float4*)(bp + c4 * 4);
                split_pack4(bv, h, l);
                *(uint2*)&sBhi[lrow * LDS_ROW + lcol + c4 * 4] = h;
                *(uint2*)&sBlo[lrow * LDS_ROW + lcol + c4 * 4] = l;
            }
        }
        __syncthreads();

#pragma unroll
        for (int ks = 0; ks < 2; ks++) {          // two k16 steps per BK=32
            const int kb = ks * 16;

            // A fragments: [am] x {a0..a3} for hi and lo
            uint32_t Ahi[4][4], Alo[4][4];
#pragma unroll
            for (int am = 0; am < 4; am++) {
                const int r0 = (wm + am * 16 + gid) * LDS_ROW + kb + tig * 2;
                const int r8 = r0 + 8 * LDS_ROW;
                Ahi[am][0] = *(const uint32_t*)&sAhi[r0];
                Ahi[am][1] = *(const uint32_t*)&sAhi[r8];
                Ahi[am][2] = *(const uint32_t*)&sAhi[r0 + 8];
                Ahi[am][3] = *(const uint32_t*)&sAhi[r8 + 8];
                Alo[am][0] = *(const uint32_t*)&sAlo[r0];
                Alo[am][1] = *(const uint32_t*)&sAlo[r8];
                Alo[am][2] = *(const uint32_t*)&sAlo[r0 + 8];
                Alo[am][3] = *(const uint32_t*)&sAlo[r8 + 8];
            }
            // B fragments: [an] x {b0,b1}
            uint32_t Bhi[4][2], Blo[4][2];
#pragma unroll
            for (int an = 0; an < 4; an++) {
                const int r = (wn + an * 8 + gid) * LDS_ROW + kb + tig * 2;
                Bhi[an][0] = *(const uint32_t*)&sBhi[r];
                Bhi[an][1] = *(const uint32_t*)&sBhi[r + 8];
                Blo[an][0] = *(const uint32_t*)&sBlo[r];
                Blo[an][1] = *(const uint32_t*)&sBlo[r + 8];
            }

#pragma unroll
            for (int am = 0; am < 4; am++)
#pragma unroll
                for (int an = 0; an < 4; an++) {
                    mma16816(acc[am][an],
                             Ahi[am][0], Ahi[am][1], Ahi[am][2], Ahi[am][3],
                             Bhi[an][0], Bhi[an][1]);
                    mma16816(acc[am][an],
                             Ahi[am][0], Ahi[am][1], Ahi[am][2], Ahi[am][3],
                             Blo[an][0], Blo[an][1]);
                    mma16816(acc[am][an],
                             Alo[am][0], Alo[am][1], Alo[am][2], Alo[am][3],
                             Bhi[an][0], Bhi[an][1]);
                }
        }
    }

    // Epilogue: c0,c1 -> (row, col..col+1); c2,c3 -> (row+8, same cols)
#pragma unroll
    for (int am = 0; am < 4; am++) {
        const int row = bm + wm + am * 16 + gid;
#pragma unroll
        for (int an = 0; an < 4; an++) {
            const int col = bn + wn + an * 8 + tig * 2;
            const float b0 = bias[col], b1 = bias[col + 1];
            float2 o0 = {acc[am][an][0] + b0, acc[am][an][1] + b1};
            float2 o1 = {acc[am][an][2] + b0, acc[am][an][3] + b1};
            *(float2*)(C + (size_t)row * 1024 + col) = o0;
            *(float2*)(C + (size_t)(row + 8) * 1024 + col) = o1;
        }
    }
}

// ===========================================================================
// Flash attention (same as R1 passing version)
// ===========================================================================
__global__ __launch_bounds__(128) void flash_attn(
    const float* __restrict__ Q, const float* __restrict__ K,
    const float* __restrict__ V, const int* __restrict__ kpm,
    float* __restrict__ O)
{
    const int b = blockIdx.z;
    const int h = blockIdx.y;
    const int qrow = blockIdx.x * 128 + threadIdx.x;

    __shared__ float Ks[64][64];
    __shared__ float Vs[64][64];
    __shared__ int   msk[64];

    const float scale = 0.125f;  // HD^-0.5, HD=64

    float q[64];
    {
        const float* qp = Q + ((size_t)b * SQL + qrow) * DMODEL + h * HDIM;
#pragma unroll
        for (int d4 = 0; d4 < 16; d4++) {
            float4 v = *(const float4*)(qp + d4 * 4);
            q[d4 * 4 + 0] = v.x * scale;
            q[d4 * 4 + 1] = v.y * scale;
            q[d4 * 4 + 2] = v.z * scale;
            q[d4 * 4 + 3] = v.w * scale;
        }
    }

    float acc[64];
#pragma unroll
    for (int d = 0; d < 64; d++) acc[d] = 0.f;
    float m = -1e30f, l = 0.f;

    for (int kt = 0; kt < SKL; kt += 64) {
        __syncthreads();
#pragma unroll
        for (int i = 0; i < 8; i++) {
            const int idx = threadIdx.x + i * 128;
            const int r = idx >> 4;
            const int c = (idx & 15) << 2;
            *(float4*)&Ks[r][c] =
                *(const float4*)(K + ((size_t)b * SKL + kt + r) * DMODEL + h * HDIM + c);
            *(float4*)&Vs[r][c] =
                *(const float4*)(V + ((size_t)b * SKL + kt + r) * DMODEL + h * HDIM + c);
        }
        if (threadIdx.x < 64) msk[threadIdx.x] = kpm[b * SKL + kt + threadIdx.x];
        __syncthreads();

        for (int j = 0; j < 64; j++) {
            if (msk[j] == 0) continue;

            float s0 = 0.f, s1 = 0.f, s2 = 0.f, s3 = 0.f;
#pragma unroll
            for (int d4 = 0; d4 < 16; d4++) {
                float4 kv = *(const float4*)&Ks[j][d4 * 4];
                s0 = fmaf(q[d4 * 4 + 0], kv.x, s0);
                s1 = fmaf(q[d4 * 4 + 1], kv.y, s1);
                s2 = fmaf(q[d4 * 4 + 2], kv.z, s2);
                s3 = fmaf(q[d4 * 4 + 3], kv.w, s3);
            }
            const float s = (s0 + s1) + (s2 + s3);

            if (s > m) {
                const float corr = __expf(m - s);
                m = s;
                l *= corr;
#pragma unroll
                for (int d = 0; d < 64; d++) acc[d] *= corr;
            }
            const float p = __expf(s - m);
            l += p;
#pragma unroll
            for (int d4 = 0; d4 < 16; d4++) {
                float4 vv = *(const float4*)&Vs[j][d4 * 4];
                acc[d4 * 4 + 0] = fmaf(p, vv.x, acc[d4 * 4 + 0]);
                acc[d4 * 4 + 1] = fmaf(p, vv.y, acc[d4 * 4 + 1]);
                acc[d4 * 4 + 2] = fmaf(p, vv.z, acc[d4 * 4 + 2]);
                acc[d4 * 4 + 3] = fmaf(p, vv.w, acc[d4 * 4 + 3]);
            }
        }
    }

    const float inv = 1.f / l;
    float* op = O + ((size_t)b * SQL + qrow) * DMODEL + h * HDIM;
#pragma unroll
    for (int d4 = 0; d4 < 16; d4++) {
        float4 o;
        o.x = acc[d4 * 4 + 0] * inv;
        o.y = acc[d4 * 4 + 1] * inv;
        o.z = acc[d4 * 4 + 2] * inv;
        o.w = acc[d4 * 4 + 3] * inv;
        *(float4*)(op + d4 * 4) = o;
    }
}

// ---------------------------------------------------------------------------
extern "C" void kernel_launch(void* const* d_in, const int* in_sizes, int n_in,
                              void* d_out, int out_size)
{
    const float* query = (const float*)d_in[0];
    const float* key   = (const float*)d_in[1];
    const float* value = (const float*)d_in[2];
    const int*   kpm   = (const int*)  d_in[3];
    const float* Wq    = (const float*)d_in[4];
    const float* bq    = (const float*)d_in[5];
    const float* Wk    = (const float*)d_in[6];
    const float* bk    = (const float*)d_in[7];
    const float* Wv    = (const float*)d_in[8];
    const float* bv    = (const float*)d_in[9];
    const float* Wo    = (const float*)d_in[10];
    const float* bo    = (const float*)d_in[11];
    float* out = (float*)d_out;

    float *Qp, *Kp, *Vp, *AOp;
    cudaGetSymbolAddress((void**)&Qp,  g_Q);
    cudaGetSymbolAddress((void**)&Kp,  g_K);
    cudaGetSymbolAddress((void**)&Vp,  g_V);
    cudaGetSymbolAddress((void**)&AOp, g_AO);

    dim3 gGemm(DMODEL / 128, (BB * SQL) / 128);   // (8, 64)

    gemm_tc<<<gGemm, 256>>>(query, Wq, bq, Qp);
    gemm_tc<<<gGemm, 256>>>(key,   Wk, bk, Kp);
    gemm_tc<<<gGemm, 256>>>(value, Wv, bv, Vp);

    dim3 gAttn(SQL / 128, NH, BB);                // (16, 16, 4)
    flash_attn<<<gAttn, 128>>>(Qp, Kp, Vp, kpm, AOp);

    gemm_tc<<<gGemm, 256>>>(AOp, Wo, bo, out);
}

// round 4
// speedup vs baseline: 4.6921x; 2.2275x over previous
#include <cuda_runtime.h>
#include <cuda_bf16.h>
#include <cstdint>

#define BB     4
#define SQL    2048
#define SKL    2048
#define DMODEL 1024
#define NH     16
#define HDIM   64
#define NKMAX  2048

// f32 scratch
__device__ float g_Q [(size_t)BB * SQL * DMODEL];
__device__ float g_K [(size_t)BB * SKL * DMODEL];
__device__ float g_V [(size_t)BB * SKL * DMODEL];
__device__ float g_AO[(size_t)BB * SQL * DMODEL];
// bf16 split scratch
__device__ __nv_bfloat16 g_Qhi[(size_t)BB * SQL * DMODEL];
__device__ __nv_bfloat16 g_Qlo[(size_t)BB * SQL * DMODEL];
__device__ __nv_bfloat16 g_Khi[(size_t)BB * SKL * DMODEL];
__device__ __nv_bfloat16 g_Klo[(size_t)BB * SKL * DMODEL];
__device__ __nv_bfloat16 g_Vthi[(size_t)BB * NH * HDIM * NKMAX];
__device__ __nv_bfloat16 g_Vtlo[(size_t)BB * NH * HDIM * NKMAX];
__device__ int g_kidx[BB * SKL];
__device__ int g_knum[BB];

// ===========================================================================
// HMMA m16n8k16 bf16 -> fp32
// ===========================================================================
__device__ __forceinline__ void mma16816(float c[4],
                                         uint32_t a0, uint32_t a1,
                                         uint32_t a2, uint32_t a3,
                                         uint32_t b0, uint32_t b1) {
    asm volatile(
        "mma.sync.aligned.m16n8k16.row.col.f32.bf16.bf16.f32 "
        "{%0,%1,%2,%3}, {%4,%5,%6,%7}, {%8,%9}, {%0,%1,%2,%3};"
        : "+f"(c[0]), "+f"(c[1]), "+f"(c[2]), "+f"(c[3])
        : "r"(a0), "r"(a1), "r"(a2), "r"(a3), "r"(b0), "r"(b1));
}

__device__ __forceinline__ uint32_t pack_bf16(float a, float b) {
    __nv_bfloat16 ha = __float2bfloat16_rn(a);
    __nv_bfloat16 hb = __float2bfloat16_rn(b);
    return ((uint32_t)__bfloat16_as_ushort(hb) << 16) | __bfloat16_as_ushort(ha);
}

__device__ __forceinline__ void split_pack4(float4 v, uint2& h, uint2& l) {
    __nv_bfloat16 hx = __float2bfloat16_rn(v.x);
    __nv_bfloat16 hy = __float2bfloat16_rn(v.y);
    __nv_bfloat16 hz = __float2bfloat16_rn(v.z);
    __nv_bfloat16 hw = __float2bfloat16_rn(v.w);
    __nv_bfloat16 lx = __float2bfloat16_rn(v.x - __bfloat162float(hx));
    __nv_bfloat16 ly = __float2bfloat16_rn(v.y - __bfloat162float(hy));
    __nv_bfloat16 lz = __float2bfloat16_rn(v.z - __bfloat162float(hz));
    __nv_bfloat16 lw = __float2bfloat16_rn(v.w - __bfloat162float(hw));
    h.x = ((uint32_t)__bfloat16_as_ushort(hy) << 16) | __bfloat16_as_ushort(hx);
    h.y = ((uint32_t)__bfloat16_as_ushort(hw) << 16) | __bfloat16_as_ushort(hz);
    l.x = ((uint32_t)__bfloat16_as_ushort(ly) << 16) | __bfloat16_as_ushort(lx);
    l.y = ((uint32_t)__bfloat16_as_ushort(lw) << 16) | __bfloat16_as_ushort(lz);
}

// ===========================================================================
// Projection GEMM (unchanged from R3 — working)
// ===========================================================================
#define BK      32
#define LDS_ROW 40

__global__ __launch_bounds__(256) void gemm_tc(
    const float* __restrict__ A, const float* __restrict__ W,
    const float* __restrict__ bias, float* __restrict__ C)
{
    __shared__ __nv_bfloat16 sAhi[128 * LDS_ROW];
    __shared__ __nv_bfloat16 sAlo[128 * LDS_ROW];
    __shared__ __nv_bfloat16 sBhi[128 * LDS_ROW];
    __shared__ __nv_bfloat16 sBlo[128 * LDS_ROW];

    const int tid  = threadIdx.x;
    const int w    = tid >> 5;
    const int lane = tid & 31;
    const int gid  = lane >> 2;
    const int tig  = lane & 3;
    const int bm   = blockIdx.y * 128;
    const int bn   = blockIdx.x * 128;
    const int wm = (w & 1) * 64;
    const int wn = (w >> 1) * 32;

    float acc[4][4][4];
#pragma unroll
    for (int i = 0; i < 4; i++)
#pragma unroll
        for (int j = 0; j < 4; j++)
#pragma unroll
            for (int k = 0; k < 4; k++) acc[i][j][k] = 0.f;

    const int lrow = tid >> 1;
    const int lcol = (tid & 1) * 16;

    for (int k0 = 0; k0 < 1024; k0 += BK) {
        __syncthreads();
        {
            const float* ap = A + (size_t)(bm + lrow) * 1024 + k0 + lcol;
            const float* bp = W + (size_t)(bn + lrow) * 1024 + k0 + lcol;
#pragma unroll
            for (int c4 = 0; c4 < 4; c4++) {
                uint2 h, l;
                float4 av = *(const float4*)(ap + c4 * 4);
                split_pack4(av, h, l);
                *(uint2*)&sAhi[lrow * LDS_ROW + lcol + c4 * 4] = h;
                *(uint2*)&sAlo[lrow * LDS_ROW + lcol + c4 * 4] = l;
                float4 bv = *(const float4*)(bp + c4 * 4);
                split_pack4(bv, h, l);
                *(uint2*)&sBhi[lrow * LDS_ROW + lcol + c4 * 4] = h;
                *(uint2*)&sBlo[lrow * LDS_ROW + lcol + c4 * 4] = l;
            }
        }
        __syncthreads();

#pragma unroll
        for (int ks = 0; ks < 2; ks++) {
            const int kb = ks * 16;
            uint32_t Ahi[4][4], Alo[4][4];
#pragma unroll
            for (int am = 0; am < 4; am++) {
                const int r0 = (wm + am * 16 + gid) * LDS_ROW + kb + tig * 2;
                const int r8 = r0 + 8 * LDS_ROW;
                Ahi[am][0] = *(const uint32_t*)&sAhi[r0];
                Ahi[am][1] = *(const uint32_t*)&sAhi[r8];
                Ahi[am][2] = *(const uint32_t*)&sAhi[r0 + 8];
                Ahi[am][3] = *(const uint32_t*)&sAhi[r8 + 8];
                Alo[am][0] = *(const uint32_t*)&sAlo[r0];
                Alo[am][1] = *(const uint32_t*)&sAlo[r8];
                Alo[am][2] = *(const uint32_t*)&sAlo[r0 + 8];
                Alo[am][3] = *(const uint32_t*)&sAlo[r8 + 8];
            }
            uint32_t Bhi[4][2], Blo[4][2];
#pragma unroll
            for (int an = 0; an < 4; an++) {
                const int r = (wn + an * 8 + gid) * LDS_ROW + kb + tig * 2;
                Bhi[an][0] = *(const uint32_t*)&sBhi[r];
                Bhi[an][1] = *(const uint32_t*)&sBhi[r + 8];
                Blo[an][0] = *(const uint32_t*)&sBlo[r];
                Blo[an][1] = *(const uint32_t*)&sBlo[r + 8];
            }
#pragma unroll
            for (int am = 0; am < 4; am++)
#pragma unroll
                for (int an = 0; an < 4; an++) {
                    mma16816(acc[am][an],
                             Ahi[am][0], Ahi[am][1], Ahi[am][2], Ahi[am][3],
                             Bhi[an][0], Bhi[an][1]);
                    mma16816(acc[am][an],
                             Ahi[am][0], Ahi[am][1], Ahi[am][2], Ahi[am][3],
                             Blo[an][0], Blo[an][1]);
                    mma16816(acc[am][an],
                             Alo[am][0], Alo[am][1], Alo[am][2], Alo[am][3],
                             Bhi[an][0], Bhi[an][1]);
                }
        }
    }

#pragma unroll
    for (int am = 0; am < 4; am++) {
        const int row = bm + wm + am * 16 + gid;
#pragma unroll
        for (int an = 0; an < 4; an++) {
            const int col = bn + wn + an * 8 + tig * 2;
            const float b0 = bias[col], b1 = bias[col + 1];
            float2 o0 = {acc[am][an][0] + b0, acc[am][an][1] + b1};
            float2 o1 = {acc[am][an][2] + b0, acc[am][an][3] + b1};
            *(float2*)(C + (size_t)row * 1024 + col) = o0;
            *(float2*)(C + (size_t)(row + 8) * 1024 + col) = o1;
        }
    }
}

// ===========================================================================
// Prep: mask scan (1 block / batch)
// ===========================================================================
__global__ __launch_bounds__(256) void scan_mask(const int* __restrict__ kpm) {
    const int b = blockIdx.x, t = threadIdx.x;
    __shared__ int cnt[256];
    int loc[8], c = 0;
#pragma unroll
    for (int i = 0; i < 8; i++) {
        loc[i] = (kpm[b * SKL + t * 8 + i] != 0) ? 1 : 0;
        c += loc[i];
    }
    cnt[t] = c;
    __syncthreads();
    for (int off = 1; off < 256; off <<= 1) {
        int v = (t >= off) ? cnt[t - off] : 0;
        __syncthreads();
        cnt[t] += v;
        __syncthreads();
    }
    int pos = cnt[t] - c;    // exclusive prefix
#pragma unroll
    for (int i = 0; i < 8; i++) {
        if (loc[i]) g_kidx[b * SKL + pos++] = t * 8 + i;
    }
    if (t == 255) g_knum[b] = cnt[255];
}

// ===========================================================================
// Prep: Q scale+split  (grid = BB*SQL rows, 256 thr)
// ===========================================================================
__global__ __launch_bounds__(256) void prep_q() {
    const size_t r = blockIdx.x;
    const int t = threadIdx.x;
    float4 v = *(const float4*)&g_Q[r * 1024 + t * 4];
    v.x *= 0.125f; v.y *= 0.125f; v.z *= 0.125f; v.w *= 0.125f;
    uint2 h, l;
    split_pack4(v, h, l);
    *(uint2*)&g_Qhi[r * 1024 + t * 4] = h;
    *(uint2*)&g_Qlo[r * 1024 + t * 4] = l;
}

// ===========================================================================
// Prep: K gather+split  (grid (SKL, BB), 256 thr)
// ===========================================================================
__global__ __launch_bounds__(256) void prep_k() {
    const int j = blockIdx.x, b = blockIdx.y, t = threadIdx.x;
    const int nv  = g_knum[b];
    const int nkp = (nv + 63) & ~63;
    if (j >= nkp) return;
    uint2 h = {0u, 0u}, l = {0u, 0u};
    if (j < nv) {
        const int src = g_kidx[b * SKL + j];
        float4 v = *(const float4*)&g_K[((size_t)b * SKL + src) * 1024 + t * 4];
        split_pack4(v, h, l);
    }
    *(uint2*)&g_Khi[((size_t)b * SKL + j) * 1024 + t * 4] = h;
    *(uint2*)&g_Klo[((size_t)b * SKL + j) * 1024 + t * 4] = l;
}

// ===========================================================================
// Prep: V gather + transpose + split -> Vt[b][h][d][key]
// grid (SKL/64, NH, BB), 256 thr
// ===========================================================================
__global__ __launch_bounds__(256) void prep_vt() {
    const int b = blockIdx.z, h = blockIdx.y, j0 = blockIdx.x * 64;
    const int nv  = g_knum[b];
    const int nkp = (nv + 63) & ~63;
    if (j0 >= nkp) return;
    __shared__ float tile[64][65];
    const int t = threadIdx.x;
#pragma unroll
    for (int p = 0; p < 4; p++) {
        const int r = p * 16 + (t >> 4);      // key-in-tile
        const int c = (t & 15) * 4;           // d
        const int j = j0 + r;
        float4 v = {0.f, 0.f, 0.f, 0.f};
        if (j < nv) {
            const int src = g_kidx[b * SKL + j];
            v = *(const float4*)&g_V[((size_t)b * SKL + src) * 1024 + h * 64 + c];
        }
        tile[c + 0][r] = v.x; tile[c + 1][r] = v.y;
        tile[c + 2][r] = v.z; tile[c + 3][r] = v.w;
    }
    __syncthreads();
    const int d = t >> 2, jg = (t & 3) * 16;
    ushort hi[16], lo[16];
#pragma unroll
    for (int i = 0; i < 16; i++) {
        float v = tile[d][jg + i];
        __nv_bfloat16 hb = __float2bfloat16_rn(v);
        __nv_bfloat16 lb = __float2bfloat16_rn(v - __bfloat162float(hb));
        hi[i] = __bfloat16_as_ushort(hb);
        lo[i] = __bfloat16_as_ushort(lb);
    }
    const size_t base = (((size_t)(b * NH + h)) * 64 + d) * NKMAX + j0 + jg;
    *(uint4*)&g_Vthi[base] = *(uint4*)hi;
    *(uint4*)&g_Vtlo[base] = *(uint4*)lo;
    *(uint4*)&g_Vthi[base + 8] = *(uint4*)&hi[8];
    *(uint4*)&g_Vtlo[base + 8] = *(uint4*)&lo[8];
}

// ===========================================================================
// Tensor-core flash attention over compacted keys.
// CTA = (b, h, 128 q rows); 8 warps x 16 rows; chunks of 64 keys.
// ===========================================================================
#define FLDS 72   // bf16 per smem row (64 data + 8 pad)

__global__ __launch_bounds__(256) void flash_tc() {
    // 4 buffers of [64][FLDS] bf16 = 36,864 B; Q staged through same space.
    __shared__ __nv_bfloat16 sbuf[4 * 64 * FLDS];
    __nv_bfloat16* sKh = sbuf;
    __nv_bfloat16* sKl = sbuf + 64 * FLDS;
    __nv_bfloat16* sVh = sbuf + 2 * 64 * FLDS;
    __nv_bfloat16* sVl = sbuf + 3 * 64 * FLDS;

    const int b = blockIdx.z, h = blockIdx.y, q0 = blockIdx.x * 128;
    const int tid = threadIdx.x;
    const int w = tid >> 5, lane = tid & 31;
    const int gid = lane >> 2, tig = lane & 3;

    const int nv  = g_knum[b];
    const int nkp = (nv + 63) & ~63;

    // ---- Stage Q (128x64 hi+lo) into sbuf, pull fragments to registers ----
    {
        const int r = tid >> 1, c0 = (tid & 1) * 32;
        const size_t gbase = ((size_t)b * SQL + q0 + r) * 1024 + h * 64 + c0;
        __nv_bfloat16* qh = sbuf + r * FLDS + c0;                 // [128][FLDS]
        __nv_bfloat16* ql = sbuf + 128 * FLDS + r * FLDS + c0;
#pragma unroll
        for (int u = 0; u < 4; u++) {
            *(uint4*)&qh[u * 8] = *(const uint4*)&g_Qhi[gbase + u * 8];
            *(uint4*)&ql[u * 8] = *(const uint4*)&g_Qlo[gbase + u * 8];
        }
    }
    __syncthreads();

    uint32_t Qh[4][4], Ql[4][4];
    {
        const int qr = w * 16 + gid;
#pragma unroll
        for (int ks = 0; ks < 4; ks++) {
            const int base = qr * FLDS + ks * 16 + tig * 2;
            Qh[ks][0] = *(const uint32_t*)&sbuf[base];
            Qh[ks][1] = *(const uint32_t*)&sbuf[base + 8 * FLDS];
            Qh[ks][2] = *(const uint32_t*)&sbuf[base + 8];
            Qh[ks][3] = *(const uint32_t*)&sbuf[base + 8 * FLDS + 8];
            Ql[ks][0] = *(const uint32_t*)&sbuf[128 * FLDS + base];
            Ql[ks][1] = *(const uint32_t*)&sbuf[128 * FLDS + base + 8 * FLDS];
            Ql[ks][2] = *(const uint32_t*)&sbuf[128 * FLDS + base + 8];
            Ql[ks][3] = *(const uint32_t*)&sbuf[128 * FLDS + base + 8 * FLDS + 8];
        }
    }

    float Oa[8][4];
#pragma unroll
    for (int i = 0; i < 8; i++)
#pragma unroll
        for (int j = 0; j < 4; j++) Oa[i][j] = 0.f;
    float m0 = -1e30f, m1 = -1e30f, l0 = 0.f, l1 = 0.f;

    for (int kt = 0; kt < nkp; kt += 64) {
        __syncthreads();
        // ---- load K / Vt chunk ----
        {
            const int r = tid >> 2, c0 = (tid & 3) * 16;
            const size_t kb = ((size_t)b * SKL + kt + r) * 1024 + h * 64 + c0;
            *(uint4*)&sKh[r * FLDS + c0]     = *(const uint4*)&g_Khi[kb];
            *(uint4*)&sKh[r * FLDS + c0 + 8] = *(const uint4*)&g_Khi[kb + 8];
            *(uint4*)&sKl[r * FLDS + c0]     = *(const uint4*)&g_Klo[kb];
            *(uint4*)&sKl[r * FLDS + c0 + 8] = *(const uint4*)&g_Klo[kb + 8];
            const size_t vb = (((size_t)(b * NH + h)) * 64 + r) * NKMAX + kt + c0;
            *(uint4*)&sVh[r * FLDS + c0]     = *(const uint4*)&g_Vthi[vb];
            *(uint4*)&sVh[r * FLDS + c0 + 8] = *(const uint4*)&g_Vthi[vb + 8];
            *(uint4*)&sVl[r * FLDS + c0]     = *(const uint4*)&g_Vtlo[vb];
            *(uint4*)&sVl[r * FLDS + c0 + 8] = *(const uint4*)&g_Vtlo[vb + 8];
        }
        __syncthreads();

        // ---- S = Q K^T (128x64 tile; this warp: 16 rows x 64 keys) ----
        float S[8][4];
#pragma unroll
        for (int i = 0; i < 8; i++)
#pragma unroll
            for (int j = 0; j < 4; j++) S[i][j] = 0.f;

#pragma unroll
        for (int ks = 0; ks < 4; ks++) {
#pragma unroll
            for (int nt = 0; nt < 8; nt++) {
                const int kb = (nt * 8 + gid) * FLDS + ks * 16 + tig * 2;
                const uint32_t bh0 = *(const uint32_t*)&sKh[kb];
                const uint32_t bh1 = *(const uint32_t*)&sKh[kb + 8];
                const uint32_t bl0 = *(const uint32_t*)&sKl[kb];
                const uint32_t bl1 = *(const uint32_t*)&sKl[kb + 8];
                mma16816(S[nt], Qh[ks][0], Qh[ks][1], Qh[ks][2], Qh[ks][3], bh0, bh1);
                mma16816(S[nt], Qh[ks][0], Qh[ks][1], Qh[ks][2], Qh[ks][3], bl0, bl1);
                mma16816(S[nt], Ql[ks][0], Ql[ks][1], Ql[ks][2], Ql[ks][3], bh0, bh1);
            }
        }

        // ---- tail mask ----
        if (kt + 64 > nv) {
#pragma unroll
            for (int nt = 0; nt < 8; nt++) {
                const int col = kt + nt * 8 + tig * 2;
                if (col >= nv)     { S[nt][0] = -1e30f; S[nt][2] = -1e30f; }
                if (col + 1 >= nv) { S[nt][1] = -1e30f; S[nt][3] = -1e30f; }
            }
        }

        // ---- online softmax (rows gid / gid+8 of this warp) ----
        float mx0 = -1e30f, mx1 = -1e30f;
#pragma unroll
        for (int nt = 0; nt < 8; nt++) {
            mx0 = fmaxf(mx0, fmaxf(S[nt][0], S[nt][1]));
            mx1 = fmaxf(mx1, fmaxf(S[nt][2], S[nt][3]));
        }
        mx0 = fmaxf(mx0, __shfl_xor_sync(0xffffffffu, mx0, 1));
        mx0 = fmaxf(mx0, __shfl_xor_sync(0xffffffffu, mx0, 2));
        mx1 = fmaxf(mx1, __shfl_xor_sync(0xffffffffu, mx1, 1));
        mx1 = fmaxf(mx1, __shfl_xor_sync(0xffffffffu, mx1, 2));

        const float mn0 = fmaxf(m0, mx0), mn1 = fmaxf(m1, mx1);
        const float corr0 = __expf(m0 - mn0), corr1 = __expf(m1 - mn1);
        m0 = mn0; m1 = mn1;

        float sum0 = 0.f, sum1 = 0.f;
        uint32_t Ph[4][4], Pl[4][4];
#pragma unroll
        for (int nt = 0; nt < 8; nt++) {
            const float p0 = __expf(S[nt][0] - m0);
            const float p1 = __expf(S[nt][1] - m0);
            const float p2 = __expf(S[nt][2] - m1);
            const float p3 = __expf(S[nt][3] - m1);
            sum0 += p0 + p1; sum1 += p2 + p3;
            // hi/lo split of p
            const float h0 = __bfloat162float(__float2bfloat16_rn(p0));
            const float h1 = __bfloat162float(__float2bfloat16_rn(p1));
            const float h2 = __bfloat162float(__float2bfloat16_rn(p2));
            const float h3 = __bfloat162float(__float2bfloat16_rn(p3));
            const uint32_t hi01 = pack_bf16(h0, h1);
            const uint32_t hi23 = pack_bf16(h2, h3);
            const uint32_t lo01 = pack_bf16(p0 - h0, p1 - h1);
            const uint32_t lo23 = pack_bf16(p2 - h2, p3 - h3);
            const int ks = nt >> 1;
            if ((nt & 1) == 0) {
                Ph[ks][0] = hi01; Ph[ks][1] = hi23;
                Pl[ks][0] = lo01; Pl[ks][1] = lo23;
            } else {
                Ph[ks][2] = hi01; Ph[ks][3] = hi23;
                Pl[ks][2] = lo01; Pl[ks][3] = lo23;
            }
        }
        sum0 += __shfl_xor_sync(0xffffffffu, sum0, 1);
        sum0 += __shfl_xor_sync(0xffffffffu, sum0, 2);
        sum1 += __shfl_xor_sync(0xffffffffu, sum1, 1);
        sum1 += __shfl_xor_sync(0xffffffffu, sum1, 2);
        l0 = l0 * corr0 + sum0;
        l1 = l1 * corr1 + sum1;

#pragma unroll
        for (int nt = 0; nt < 8; nt++) {
            Oa[nt][0] *= corr0; Oa[nt][1] *= corr0;
            Oa[nt][2] *= corr1; Oa[nt][3] *= corr1;
        }

        // ---- O += P V  (16 rows x 64 d; keys are the k-dim) ----
#pragma unroll
        for (int ks = 0; ks < 4; ks++) {
#pragma unroll
            for (int nt = 0; nt < 8; nt++) {
                const int vb = (nt * 8 + gid) * FLDS + ks * 16 + tig * 2;
                const uint32_t bh0 = *(const uint32_t*)&sVh[vb];
                const uint32_t bh1 = *(const uint32_t*)&sVh[vb + 8];
                const uint32_t bl0 = *(const uint32_t*)&sVl[vb];
                const uint32_t bl1 = *(const uint32_t*)&sVl[vb + 8];
                mma16816(Oa[nt], Ph[ks][0], Ph[ks][1], Ph[ks][2], Ph[ks][3], bh0, bh1);
                mma16816(Oa[nt], Ph[ks][0], Ph[ks][1], Ph[ks][2], Ph[ks][3], bl0, bl1);
                mma16816(Oa[nt], Pl[ks][0], Pl[ks][1], Pl[ks][2], Pl[ks][3], bh0, bh1);
            }
        }
    }

    // ---- epilogue ----
    const float inv0 = 1.f / l0, inv1 = 1.f / l1;
    const int row0 = q0 + w * 16 + gid;
#pragma unroll
    for (int nt = 0; nt < 8; nt++) {
        const int col = h * 64 + nt * 8 + tig * 2;
        float2 o0 = {Oa[nt][0] * inv0, Oa[nt][1] * inv0};
        float2 o1 = {Oa[nt][2] * inv1, Oa[nt][3] * inv1};
        *(float2*)&g_AO[((size_t)b * SQL + row0) * 1024 + col] = o0;
        *(float2*)&g_AO[((size_t)b * SQL + row0 + 8) * 1024 + col] = o1;
    }
}

// ---------------------------------------------------------------------------
extern "C" void kernel_launch(void* const* d_in, const int* in_sizes, int n_in,
                              void* d_out, int out_size)
{
    const float* query = (const float*)d_in[0];
    const float* key   = (const float*)d_in[1];
    const float* value = (const float*)d_in[2];
    const int*   kpm   = (const int*)  d_in[3];
    const float* Wq    = (const float*)d_in[4];
    const float* bq    = (const float*)d_in[5];
    const float* Wk    = (const float*)d_in[6];
    const float* bk    = (const float*)d_in[7];
    const float* Wv    = (const float*)d_in[8];
    const float* bv    = (const float*)d_in[9];
    const float* Wo    = (const float*)d_in[10];
    const float* bo    = (const float*)d_in[11];
    float* out = (float*)d_out;

    float *Qp, *Kp, *Vp, *AOp;
    cudaGetSymbolAddress((void**)&Qp,  g_Q);
    cudaGetSymbolAddress((void**)&Kp,  g_K);
    cudaGetSymbolAddress((void**)&Vp,  g_V);
    cudaGetSymbolAddress((void**)&AOp, g_AO);

    dim3 gGemm(DMODEL / 128, (BB * SQL) / 128);   // (8, 64)

    gemm_tc<<<gGemm, 256>>>(query, Wq, bq, Qp);
    gemm_tc<<<gGemm, 256>>>(key,   Wk, bk, Kp);
    gemm_tc<<<gGemm, 256>>>(value, Wv, bv, Vp);

    scan_mask<<<BB, 256>>>(kpm);
    prep_q <<<BB * SQL, 256>>>();
    prep_k <<<dim3(SKL, BB), 256>>>();
    prep_vt<<<dim3(SKL / 64, NH, BB), 256>>>();

    flash_tc<<<dim3(SQL / 128, NH, BB), 256>>>();

    gemm_tc<<<gGemm, 256>>>(AOp, Wo, bo, out);
}

// round 5
// speedup vs baseline: 5.0622x; 1.0789x over previous
#include <cuda_runtime.h>
#include <cuda_fp16.h>
#include <cstdint>

#define BB     4
#define SQL    2048
#define SKL    2048
#define DMODEL 1024
#define NH     16
#define HDIM   64
#define NKMAX  2048

// Scratch (allocation-free __device__ globals)
__device__ float  g_Vc [(size_t)BB * SKL * DMODEL];   // compacted V (f32)
__device__ float  g_AO [(size_t)BB * SQL * DMODEL];   // attention output
__device__ __half g_Qhi[(size_t)BB * SQL * DMODEL];
__device__ __half g_Qlo[(size_t)BB * SQL * DMODEL];
__device__ __half g_Khi[(size_t)BB * SKL * DMODEL];
__device__ __half g_Klo[(size_t)BB * SKL * DMODEL];
__device__ __half g_Vthi[(size_t)BB * NH * HDIM * NKMAX];
__device__ __half g_Vtlo[(size_t)BB * NH * HDIM * NKMAX];
__device__ int g_rowmap[BB * SKL];
__device__ int g_knum[BB];

// ===========================================================================
// HMMA m16n8k16 fp16 -> fp32
// ===========================================================================
__device__ __forceinline__ void mma16816(float c[4],
                                         uint32_t a0, uint32_t a1,
                                         uint32_t a2, uint32_t a3,
                                         uint32_t b0, uint32_t b1) {
    asm volatile(
        "mma.sync.aligned.m16n8k16.row.col.f32.f16.f16.f32 "
        "{%0,%1,%2,%3}, {%4,%5,%6,%7}, {%8,%9}, {%0,%1,%2,%3};"
        : "+f"(c[0]), "+f"(c[1]), "+f"(c[2]), "+f"(c[3])
        : "r"(a0), "r"(a1), "r"(a2), "r"(a3), "r"(b0), "r"(b1));
}

__device__ __forceinline__ uint32_t pack_h2(float a, float b) {
    __half2 h = __floats2half2_rn(a, b);
    return *(uint32_t*)&h;
}

// fp32x4 -> packed fp16 hi / lo
__device__ __forceinline__ void split_pack4(float4 v, uint2& h, uint2& l) {
    __half hx = __float2half_rn(v.x);
    __half hy = __float2half_rn(v.y);
    __half hz = __float2half_rn(v.z);
    __half hw = __float2half_rn(v.w);
    h.x = pack_h2(__half2float(hx), __half2float(hy));
    h.y = pack_h2(__half2float(hz), __half2float(hw));
    l.x = pack_h2(v.x - __half2float(hx), v.y - __half2float(hy));
    l.y = pack_h2(v.z - __half2float(hz), v.w - __half2float(hw));
}

// ===========================================================================
// Prep: mask scan -> rowmap (compacted row -> source row, -1 = pad) + counts
// ===========================================================================
__global__ __launch_bounds__(256) void scan_mask(const int* __restrict__ kpm) {
    const int b = blockIdx.x, t = threadIdx.x;
    __shared__ int cnt[256];
    int loc[8], c = 0;
#pragma unroll
    for (int i = 0; i < 8; i++) {
        loc[i] = (kpm[b * SKL + t * 8 + i] != 0) ? 1 : 0;
        c += loc[i];
    }
    cnt[t] = c;
    __syncthreads();
    for (int off = 1; off < 256; off <<= 1) {
        int v = (t >= off) ? cnt[t - off] : 0;
        __syncthreads();
        cnt[t] += v;
        __syncthreads();
    }
    int pos = cnt[t] - c;
#pragma unroll
    for (int i = 0; i < 8; i++) g_rowmap[b * SKL + t * 8 + i] = -1;
    __syncthreads();
#pragma unroll
    for (int i = 0; i < 8; i++) {
        if (loc[i]) g_rowmap[b * SKL + pos++] = b * SKL + t * 8 + i;
    }
    if (t == 255) g_knum[b] = cnt[255];
}

// ===========================================================================
// Pipelined tensor-core GEMM: C[M,1024] = gather(A)[M,1024] @ W^T + bias
// CTA 128x128, BK=32, double-buffered smem, reg prefetch, 1 sync/stage.
// Output: f32 (Cf) OR split fp16 hi/lo (Chi/Clo), optional output scale,
// optional A-row gather via rowmap (pad rows -> zeros).
// ===========================================================================
#define LDSROW 40
#define G_ARR  (128 * LDSROW)
#define G_BUF  (4 * G_ARR)
#define G_SMEM (2 * G_BUF * 2)      // bytes = 81920

__device__ __forceinline__ void g_ldg(const float* ap, const float* bp,
                                      bool av, int k0,
                                      float4* ra, float4* rb) {
#pragma unroll
    for (int c4 = 0; c4 < 4; c4++) {
        ra[c4] = av ? *(const float4*)(ap + k0 + c4 * 4)
                    : make_float4(0.f, 0.f, 0.f, 0.f);
        rb[c4] = *(const float4*)(bp + k0 + c4 * 4);
    }
}

__device__ __forceinline__ void g_sts(__half* buf, int lrow, int lcol,
                                      const float4* ra, const float4* rb) {
#pragma unroll
    for (int c4 = 0; c4 < 4; c4++) {
        uint2 h, l;
        const int o = lrow * LDSROW + lcol + c4 * 4;
        split_pack4(ra[c4], h, l);
        *(uint2*)&buf[o]         = h;
        *(uint2*)&buf[G_ARR + o] = l;
        split_pack4(rb[c4], h, l);
        *(uint2*)&buf[2 * G_ARR + o] = h;
        *(uint2*)&buf[3 * G_ARR + o] = l;
    }
}

__global__ __launch_bounds__(256) void gemm_tc(
    const float* __restrict__ A, const float* __restrict__ W,
    const float* __restrict__ bias,
    float* __restrict__ Cf, __half* __restrict__ Chi, __half* __restrict__ Clo,
    float oscale, const int* __restrict__ rowmap)
{
    extern __shared__ __half gsm[];

    const int tid  = threadIdx.x;
    const int w    = tid >> 5;
    const int lane = tid & 31;
    const int gid  = lane >> 2;
    const int tig  = lane & 3;
    const int bm   = blockIdx.y * 128;
    const int bn   = blockIdx.x * 128;
    const int wm = (w & 1) * 64;
    const int wn = (w >> 1) * 32;

    float acc[4][4][4];
#pragma unroll
    for (int i = 0; i < 4; i++)
#pragma unroll
        for (int j = 0; j < 4; j++)
#pragma unroll
            for (int k = 0; k < 4; k++) acc[i][j][k] = 0.f;

    const int lrow = tid >> 1;
    const int lcol = (tid & 1) * 16;
    int srow = bm + lrow;
    if (rowmap) srow = rowmap[srow];
    const bool avalid = (srow >= 0);
    const float* ap = A + (size_t)(avalid ? srow : 0) * 1024 + lcol;
    const float* bp = W + (size_t)(bn + lrow) * 1024 + lcol;

    float4 ra[4], rb[4];
    g_ldg(ap, bp, avalid, 0, ra, rb);
    g_sts(gsm, lrow, lcol, ra, rb);

    for (int s = 0; s < 32; s++) {
        __syncthreads();
        if (s < 31) g_ldg(ap, bp, avalid, (s + 1) * 32, ra, rb);

        __half* buf = gsm + (s & 1) * G_BUF;
        __half* sAhi = buf;
        __half* sAlo = buf + G_ARR;
        __half* sBhi = buf + 2 * G_ARR;
        __half* sBlo = buf + 3 * G_ARR;

#pragma unroll
        for (int ks = 0; ks < 2; ks++) {
            const int kb = ks * 16;
            uint32_t Ahi[4][4], Alo[4][4];
#pragma unroll
            for (int am = 0; am < 4; am++) {
                const int r0 = (wm + am * 16 + gid) * LDSROW + kb + tig * 2;
                const int r8 = r0 + 8 * LDSROW;
                Ahi[am][0] = *(const uint32_t*)&sAhi[r0];
                Ahi[am][1] = *(const uint32_t*)&sAhi[r8];
                Ahi[am][2] = *(const uint32_t*)&sAhi[r0 + 8];
                Ahi[am][3] = *(const uint32_t*)&sAhi[r8 + 8];
                Alo[am][0] = *(const uint32_t*)&sAlo[r0];
                Alo[am][1] = *(const uint32_t*)&sAlo[r8];
                Alo[am][2] = *(const uint32_t*)&sAlo[r0 + 8];
                Alo[am][3] = *(const uint32_t*)&sAlo[r8 + 8];
            }
            uint32_t Bhi[4][2], Blo[4][2];
#pragma unroll
            for (int an = 0; an < 4; an++) {
                const int r = (wn + an * 8 + gid) * LDSROW + kb + tig * 2;
                Bhi[an][0] = *(const uint32_t*)&sBhi[r];
                Bhi[an][1] = *(const uint32_t*)&sBhi[r + 8];
                Blo[an][0] = *(const uint32_t*)&sBlo[r];
                Blo[an][1] = *(const uint32_t*)&sBlo[r + 8];
            }
#pragma unroll
            for (int am = 0; am < 4; am++)
#pragma unroll
                for (int an = 0; an < 4; an++) {
                    mma16816(acc[am][an],
                             Ahi[am][0], Ahi[am][1], Ahi[am][2], Ahi[am][3],
                             Bhi[an][0], Bhi[an][1]);
                    mma16816(acc[am][an],
                             Ahi[am][0], Ahi[am][1], Ahi[am][2], Ahi[am][3],
                             Blo[an][0], Blo[an][1]);
                    mma16816(acc[am][an],
                             Alo[am][0], Alo[am][1], Alo[am][2], Alo[am][3],
                             Bhi[an][0], Bhi[an][1]);
                }
        }
        if (s < 31) g_sts(gsm + ((s + 1) & 1) * G_BUF, lrow, lcol, ra, rb);
    }

    // Epilogue
#pragma unroll
    for (int am = 0; am < 4; am++) {
        const int row = bm + wm + am * 16 + gid;
        bool v0 = true, v1 = true;
        if (rowmap) {
            v0 = (rowmap[row] >= 0);
            v1 = (rowmap[row + 8] >= 0);
        }
#pragma unroll
        for (int an = 0; an < 4; an++) {
            const int col = bn + wn + an * 8 + tig * 2;
            const float b0 = bias[col], b1 = bias[col + 1];
            float o00 = v0 ? (acc[am][an][0] + b0) * oscale : 0.f;
            float o01 = v0 ? (acc[am][an][1] + b1) * oscale : 0.f;
            float o10 = v1 ? (acc[am][an][2] + b0) * oscale : 0.f;
            float o11 = v1 ? (acc[am][an][3] + b1) * oscale : 0.f;
            if (Chi) {
                __half h00 = __float2half_rn(o00), h01 = __float2half_rn(o01);
                __half h10 = __float2half_rn(o10), h11 = __float2half_rn(o11);
                *(uint32_t*)&Chi[(size_t)row * 1024 + col] =
                    pack_h2(__half2float(h00), __half2float(h01));
                *(uint32_t*)&Chi[(size_t)(row + 8) * 1024 + col] =
                    pack_h2(__half2float(h10), __half2float(h11));
                *(uint32_t*)&Clo[(size_t)row * 1024 + col] =
                    pack_h2(o00 - __half2float(h00), o01 - __half2float(h01));
                *(uint32_t*)&Clo[(size_t)(row + 8) * 1024 + col] =
                    pack_h2(o10 - __half2float(h10), o11 - __half2float(h11));
            } else {
                float2 f0 = {o00, o01}, f1 = {o10, o11};
                *(float2*)(Cf + (size_t)row * 1024 + col) = f0;
                *(float2*)(Cf + (size_t)(row + 8) * 1024 + col) = f1;
            }
        }
    }
}

// ===========================================================================
// Prep: V transpose + split -> Vt[b][h][d][key] (V already compacted)
// ===========================================================================
__global__ __launch_bounds__(256) void prep_vt() {
    const int b = blockIdx.z, h = blockIdx.y, j0 = blockIdx.x * 64;
    const int nv  = g_knum[b];
    const int nkp = (nv + 63) & ~63;
    if (j0 >= nkp) return;
    __shared__ float tile[64][65];
    const int t = threadIdx.x;
#pragma unroll
    for (int p = 0; p < 4; p++) {
        const int r = p * 16 + (t >> 4);
        const int c = (t & 15) * 4;
        float4 v = *(const float4*)&g_Vc[((size_t)b * SKL + j0 + r) * 1024 + h * 64 + c];
        tile[c + 0][r] = v.x; tile[c + 1][r] = v.y;
        tile[c + 2][r] = v.z; tile[c + 3][r] = v.w;
    }
    __syncthreads();
    const int d = t >> 2, jg = (t & 3) * 16;
    ushort hi[16], lo[16];
#pragma unroll
    for (int i = 0; i < 16; i++) {
        float v = tile[d][jg + i];
        __half hb = __float2half_rn(v);
        __half lb = __float2half_rn(v - __half2float(hb));
        hi[i] = *(ushort*)&hb;
        lo[i] = *(ushort*)&lb;
    }
    const size_t base = (((size_t)(b * NH + h)) * 64 + d) * NKMAX + j0 + jg;
    *(uint4*)&g_Vthi[base]     = *(uint4*)hi;
    *(uint4*)&g_Vtlo[base]     = *(uint4*)lo;
    *(uint4*)&g_Vthi[base + 8] = *(uint4*)&hi[8];
    *(uint4*)&g_Vtlo[base + 8] = *(uint4*)&lo[8];
}

// ===========================================================================
// Pipelined tensor-core flash attention over compacted keys.
// CTA = (b, h, 128 q rows); 8 warps x 16 rows; 64-key chunks, double buffer.
// ===========================================================================
#define FLDS  72
#define F_CH  (64 * FLDS)
#define F_BUF (4 * F_CH)
#define F_SMEM (2 * F_BUF * 2)      // bytes = 73728

__device__ __forceinline__ void f_ldg(int b, int h, int kt, int r, int c0,
                                      uint4* rg) {
    const size_t kb = ((size_t)b * SKL + kt + r) * 1024 + h * 64 + c0;
    rg[0] = *(const uint4*)&g_Khi[kb];
    rg[1] = *(const uint4*)&g_Khi[kb + 8];
    rg[2] = *(const uint4*)&g_Klo[kb];
    rg[3] = *(const uint4*)&g_Klo[kb + 8];
    const size_t vb = (((size_t)(b * NH + h)) * 64 + r) * NKMAX + kt + c0;
    rg[4] = *(const uint4*)&g_Vthi[vb];
    rg[5] = *(const uint4*)&g_Vthi[vb + 8];
    rg[6] = *(const uint4*)&g_Vtlo[vb];
    rg[7] = *(const uint4*)&g_Vtlo[vb + 8];
}

__device__ __forceinline__ void f_sts(__half* buf, int r, int c0,
                                      const uint4* rg) {
    const int o = r * FLDS + c0;
    *(uint4*)&buf[o]              = rg[0];
    *(uint4*)&buf[o + 8]          = rg[1];
    *(uint4*)&buf[F_CH + o]       = rg[2];
    *(uint4*)&buf[F_CH + o + 8]   = rg[3];
    *(uint4*)&buf[2 * F_CH + o]     = rg[4];
    *(uint4*)&buf[2 * F_CH + o + 8] = rg[5];
    *(uint4*)&buf[3 * F_CH + o]     = rg[6];
    *(uint4*)&buf[3 * F_CH + o + 8] = rg[7];
}

__global__ __launch_bounds__(256) void flash_tc() {
    extern __shared__ __half fsm[];

    const int b = blockIdx.z, h = blockIdx.y, q0 = blockIdx.x * 128;
    const int tid = threadIdx.x;
    const int w = tid >> 5, lane = tid & 31;
    const int gid = lane >> 2, tig = lane & 3;

    const int nv  = g_knum[b];
    const int nkp = (nv + 63) & ~63;

    // ---- Stage Q through buffer 0, pull fragments ----
    {
        const int r = tid >> 1, c0 = (tid & 1) * 32;
        const size_t gbase = ((size_t)b * SQL + q0 + r) * 1024 + h * 64 + c0;
        __half* qh = fsm + r * FLDS + c0;
        __half* ql = fsm + 128 * FLDS + r * FLDS + c0;
#pragma unroll
        for (int u = 0; u < 4; u++) {
            *(uint4*)&qh[u * 8] = *(const uint4*)&g_Qhi[gbase + u * 8];
            *(uint4*)&ql[u * 8] = *(const uint4*)&g_Qlo[gbase + u * 8];
        }
    }
    __syncthreads();

    uint32_t Qh[4][4], Ql[4][4];
    {
        const int qr = w * 16 + gid;
#pragma unroll
        for (int ks = 0; ks < 4; ks++) {
            const int base = qr * FLDS + ks * 16 + tig * 2;
            Qh[ks][0] = *(const uint32_t*)&fsm[base];
            Qh[ks][1] = *(const uint32_t*)&fsm[base + 8 * FLDS];
            Qh[ks][2] = *(const uint32_t*)&fsm[base + 8];
            Qh[ks][3] = *(const uint32_t*)&fsm[base + 8 * FLDS + 8];
            Ql[ks][0] = *(const uint32_t*)&fsm[128 * FLDS + base];
            Ql[ks][1] = *(const uint32_t*)&fsm[128 * FLDS + base + 8 * FLDS];
            Ql[ks][2] = *(const uint32_t*)&fsm[128 * FLDS + base + 8];
            Ql[ks][3] = *(const uint32_t*)&fsm[128 * FLDS + base + 8 * FLDS + 8];
        }
    }
    __syncthreads();   // everyone done reading Q before buffer 0 is reused

    float Oa[8][4];
#pragma unroll
    for (int i = 0; i < 8; i++)
#pragma unroll
        for (int j = 0; j < 4; j++) Oa[i][j] = 0.f;
    float m0 = -1e30f, m1 = -1e30f, l0 = 0.f, l1 = 0.f;

    const int lr = tid >> 2, lc0 = (tid & 3) * 16;
    uint4 rg[8];
    f_ldg(b, h, 0, lr, lc0, rg);
    f_sts(fsm, lr, lc0, rg);

    int par = 0;
    for (int kt = 0; kt < nkp; kt += 64, par ^= 1) {
        __syncthreads();
        const bool more = (kt + 64) < nkp;
        if (more) f_ldg(b, h, kt + 64, lr, lc0, rg);

        __half* buf = fsm + par * F_BUF;
        __half* sKh = buf;
        __half* sKl = buf + F_CH;
        __half* sVh = buf + 2 * F_CH;
        __half* sVl = buf + 3 * F_CH;

        // ---- S = Q K^T ----
        float S[8][4];
#pragma unroll
        for (int i = 0; i < 8; i++)
#pragma unroll
            for (int j = 0; j < 4; j++) S[i][j] = 0.f;

#pragma unroll
        for (int ks = 0; ks < 4; ks++) {
#pragma unroll
            for (int nt = 0; nt < 8; nt++) {
                const int kb = (nt * 8 + gid) * FLDS + ks * 16 + tig * 2;
                const uint32_t bh0 = *(const uint32_t*)&sKh[kb];
                const uint32_t bh1 = *(const uint32_t*)&sKh[kb + 8];
                const uint32_t bl0 = *(const uint32_t*)&sKl[kb];
                const uint32_t bl1 = *(const uint32_t*)&sKl[kb + 8];
                mma16816(S[nt], Qh[ks][0], Qh[ks][1], Qh[ks][2], Qh[ks][3], bh0, bh1);
                mma16816(S[nt], Qh[ks][0], Qh[ks][1], Qh[ks][2], Qh[ks][3], bl0, bl1);
                mma16816(S[nt], Ql[ks][0], Ql[ks][1], Ql[ks][2], Ql[ks][3], bh0, bh1);
            }
        }

        // ---- tail mask ----
        if (kt + 64 > nv) {
#pragma unroll
            for (int nt = 0; nt < 8; nt++) {
                const int col = kt + nt * 8 + tig * 2;
                if (col >= nv)     { S[nt][0] = -1e30f; S[nt][2] = -1e30f; }
                if (col + 1 >= nv) { S[nt][1] = -1e30f; S[nt][3] = -1e30f; }
            }
        }

        // ---- online softmax ----
        float mx0 = -1e30f, mx1 = -1e30f;
#pragma unroll
        for (int nt = 0; nt < 8; nt++) {
            mx0 = fmaxf(mx0, fmaxf(S[nt][0], S[nt][1]));
            mx1 = fmaxf(mx1, fmaxf(S[nt][2], S[nt][3]));
        }
        mx0 = fmaxf(mx0, __shfl_xor_sync(0xffffffffu, mx0, 1));
        mx0 = fmaxf(mx0, __shfl_xor_sync(0xffffffffu, mx0, 2));
        mx1 = fmaxf(mx1, __shfl_xor_sync(0xffffffffu, mx1, 1));
        mx1 = fmaxf(mx1, __shfl_xor_sync(0xffffffffu, mx1, 2));

        const float mn0 = fmaxf(m0, mx0), mn1 = fmaxf(m1, mx1);
        const float corr0 = __expf(m0 - mn0), corr1 = __expf(m1 - mn1);
        m0 = mn0; m1 = mn1;

        float sum0 = 0.f, sum1 = 0.f;
        uint32_t Ph[4][4], Pl[4][4];
#pragma unroll
        for (int nt = 0; nt < 8; nt++) {
            const float p0 = __expf(S[nt][0] - m0);
            const float p1 = __expf(S[nt][1] - m0);
            const float p2 = __expf(S[nt][2] - m1);
            const float p3 = __expf(S[nt][3] - m1);
            sum0 += p0 + p1; sum1 += p2 + p3;
            __half h0 = __float2half_rn(p0), h1 = __float2half_rn(p1);
            __half h2 = __float2half_rn(p2), h3 = __float2half_rn(p3);
            const float f0 = __half2float(h0), f1 = __half2float(h1);
            const float f2 = __half2float(h2), f3 = __half2float(h3);
            const uint32_t hi01 = pack_h2(f0, f1);
            const uint32_t hi23 = pack_h2(f2, f3);
            const uint32_t lo01 = pack_h2(p0 - f0, p1 - f1);
            const uint32_t lo23 = pack_h2(p2 - f2, p3 - f3);
            const int ks = nt >> 1;
            if ((nt & 1) == 0) {
                Ph[ks][0] = hi01; Ph[ks][1] = hi23;
                Pl[ks][0] = lo01; Pl[ks][1] = lo23;
            } else {
                Ph[ks][2] = hi01; Ph[ks][3] = hi23;
                Pl[ks][2] = lo01; Pl[ks][3] = lo23;
            }
        }
        sum0 += __shfl_xor_sync(0xffffffffu, sum0, 1);
        sum0 += __shfl_xor_sync(0xffffffffu, sum0, 2);
        sum1 += __shfl_xor_sync(0xffffffffu, sum1, 1);
        sum1 += __shfl_xor_sync(0xffffffffu, sum1, 2);
        l0 = l0 * corr0 + sum0;
        l1 = l1 * corr1 + sum1;

#pragma unroll
        for (int nt = 0; nt < 8; nt++) {
            Oa[nt][0] *= corr0; Oa[nt][1] *= corr0;
            Oa[nt][2] *= corr1; Oa[nt][3] *= corr1;
        }

        // ---- O += P V ----
#pragma unroll
        for (int ks = 0; ks < 4; ks++) {
#pragma unroll
            for (int nt = 0; nt < 8; nt++) {
                const int vb = (nt * 8 + gid) * FLDS + ks * 16 + tig * 2;
                const uint32_t bh0 = *(const uint32_t*)&sVh[vb];
                const uint32_t bh1 = *(const uint32_t*)&sVh[vb + 8];
                const uint32_t bl0 = *(const uint32_t*)&sVl[vb];
                const uint32_t bl1 = *(const uint32_t*)&sVl[vb + 8];
                mma16816(Oa[nt], Ph[ks][0], Ph[ks][1], Ph[ks][2], Ph[ks][3], bh0, bh1);
                mma16816(Oa[nt], Ph[ks][0], Ph[ks][1], Ph[ks][2], Ph[ks][3], bl0, bl1);
                mma16816(Oa[nt], Pl[ks][0], Pl[ks][1], Pl[ks][2], Pl[ks][3], bh0, bh1);
            }
        }

        if (more) f_sts(fsm + (par ^ 1) * F_BUF, lr, lc0, rg);
    }

    // ---- epilogue ----
    const float inv0 = 1.f / l0, inv1 = 1.f / l1;
    const int row0 = q0 + w * 16 + gid;
#pragma unroll
    for (int nt = 0; nt < 8; nt++) {
        const int col = h * 64 + nt * 8 + tig * 2;
        float2 o0 = {Oa[nt][0] * inv0, Oa[nt][1] * inv0};
        float2 o1 = {Oa[nt][2] * inv1, Oa[nt][3] * inv1};
        *(float2*)&g_AO[((size_t)b * SQL + row0) * 1024 + col] = o0;
        *(float2*)&g_AO[((size_t)b * SQL + row0 + 8) * 1024 + col] = o1;
    }
}

// ---------------------------------------------------------------------------
extern "C" void kernel_launch(void* const* d_in, const int* in_sizes, int n_in,
                              void* d_out, int out_size)
{
    const float* query = (const float*)d_in[0];
    const float* key   = (const float*)d_in[1];
    const float* value = (const float*)d_in[2];
    const int*   kpm   = (const int*)  d_in[3];
    const float* Wq    = (const float*)d_in[4];
    const float* bq    = (const float*)d_in[5];
    const float* Wk    = (const float*)d_in[6];
    const float* bk    = (const float*)d_in[7];
    const float* Wv    = (const float*)d_in[8];
    const float* bv    = (const float*)d_in[9];
    const float* Wo    = (const float*)d_in[10];
    const float* bo    = (const float*)d_in[11];
    float* out = (float*)d_out;

    float *VcP, *AOP;
    __half *QhiP, *QloP, *KhiP, *KloP;
    int *rmP;
    cudaGetSymbolAddress((void**)&VcP,  g_Vc);
    cudaGetSymbolAddress((void**)&AOP,  g_AO);
    cudaGetSymbolAddress((void**)&QhiP, g_Qhi);
    cudaGetSymbolAddress((void**)&QloP, g_Qlo);
    cudaGetSymbolAddress((void**)&KhiP, g_Khi);
    cudaGetSymbolAddress((void**)&KloP, g_Klo);
    cudaGetSymbolAddress((void**)&rmP,  g_rowmap);

    cudaFuncSetAttribute(gemm_tc, cudaFuncAttributeMaxDynamicSharedMemorySize,
                         G_SMEM);
    cudaFuncSetAttribute(flash_tc, cudaFuncAttributeMaxDynamicSharedMemorySize,
                         F_SMEM);

    dim3 gGemm(DMODEL / 128, (BB * SQL) / 128);   // (8, 64)

    scan_mask<<<BB, 256>>>(kpm);

    // Q: split output with softmax scale folded in
    gemm_tc<<<gGemm, 256, G_SMEM>>>(query, Wq, bq,
                                    nullptr, QhiP, QloP, 0.125f, nullptr);
    // K: gather + split output
    gemm_tc<<<gGemm, 256, G_SMEM>>>(key, Wk, bk,
                                    nullptr, KhiP, KloP, 1.0f, rmP);
    // V: gather, f32 compacted output
    gemm_tc<<<gGemm, 256, G_SMEM>>>(value, Wv, bv,
                                    VcP, nullptr, nullptr, 1.0f, rmP);

    prep_vt<<<dim3(SKL / 64, NH, BB), 256>>>();

    flash_tc<<<dim3(SQL / 128, NH, BB), 256, F_SMEM>>>();

    // O projection -> final output
    gemm_tc<<<gGemm, 256, G_SMEM>>>(AOP, Wo, bo,
                                    out, nullptr, nullptr, 1.0f, nullptr);
}

// round 6
// speedup vs baseline: 5.0792x; 1.0034x over previous
#include <cuda_runtime.h>
#include <cuda_fp16.h>
#include <cstdint>

#define BB     4
#define SQL    2048
#define SKL    2048
#define DMODEL 1024
#define NH     16
#define HDIM   64
#define NKMAX  2048

#define NIN  ((size_t)BB * SQL * DMODEL)   // 8M elements
#define NW   ((size_t)DMODEL * DMODEL)     // 1M elements

// Pre-split sources (fp16 hi/lo)
__device__ __half g_qsh[NIN], g_qsl[NIN];
__device__ __half g_ksh[NIN], g_ksl[NIN];
__device__ __half g_vsh[NIN], g_vsl[NIN];
__device__ __half g_wqh[NW],  g_wql[NW];
__device__ __half g_wkh[NW],  g_wkl[NW];
__device__ __half g_wvh[NW],  g_wvl[NW];
__device__ __half g_woh[NW],  g_wol[NW];
// Projected tensors
__device__ __half g_Qhi[NIN], g_Qlo[NIN];         // Q split (scale folded)
__device__ __half g_Khi[NIN], g_Klo[NIN];         // K compacted split
__device__ float  g_Vc [NIN];                     // V compacted f32
__device__ __half g_Vthi[(size_t)BB * NH * HDIM * NKMAX];
__device__ __half g_Vtlo[(size_t)BB * NH * HDIM * NKMAX];
__device__ __half g_AOhi[NIN], g_AOlo[NIN];       // attention out split
__device__ int g_rowmap[BB * SKL];
__device__ int g_knum[BB];

// ===========================================================================
// HMMA m16n8k16 fp16 -> fp32
// ===========================================================================
__device__ __forceinline__ void mma16816(float c[4],
                                         uint32_t a0, uint32_t a1,
                                         uint32_t a2, uint32_t a3,
                                         uint32_t b0, uint32_t b1) {
    asm volatile(
        "mma.sync.aligned.m16n8k16.row.col.f32.f16.f16.f32 "
        "{%0,%1,%2,%3}, {%4,%5,%6,%7}, {%8,%9}, {%0,%1,%2,%3};"
        : "+f"(c[0]), "+f"(c[1]), "+f"(c[2]), "+f"(c[3])
        : "r"(a0), "r"(a1), "r"(a2), "r"(a3), "r"(b0), "r"(b1));
}

__device__ __forceinline__ uint32_t pack_h2(float a, float b) {
    __half2 h = __floats2half2_rn(a, b);
    return *(uint32_t*)&h;
}

__device__ __forceinline__ void split_pack4(float4 v, uint2& h, uint2& l) {
    __half hx = __float2half_rn(v.x);
    __half hy = __float2half_rn(v.y);
    __half hz = __float2half_rn(v.z);
    __half hw = __float2half_rn(v.w);
    h.x = pack_h2(__half2float(hx), __half2float(hy));
    h.y = pack_h2(__half2float(hz), __half2float(hw));
    l.x = pack_h2(v.x - __half2float(hx), v.y - __half2float(hy));
    l.y = pack_h2(v.z - __half2float(hz), v.w - __half2float(hw));
}

// ===========================================================================
// Prep: elementwise fp32 -> fp16 hi/lo split
// ===========================================================================
__global__ __launch_bounds__(256) void split_src(
    const float* __restrict__ src, __half* __restrict__ hi,
    __half* __restrict__ lo)
{
    const size_t i = (size_t)blockIdx.x * 256 + threadIdx.x;
    float4 v = *(const float4*)(src + i * 4);
    uint2 h, l;
    split_pack4(v, h, l);
    *(uint2*)(hi + i * 4) = h;
    *(uint2*)(lo + i * 4) = l;
}

// ===========================================================================
// Prep: mask scan -> rowmap + counts
// ===========================================================================
__global__ __launch_bounds__(256) void scan_mask(const int* __restrict__ kpm) {
    const int b = blockIdx.x, t = threadIdx.x;
    __shared__ int cnt[256];
    int loc[8], c = 0;
#pragma unroll
    for (int i = 0; i < 8; i++) {
        loc[i] = (kpm[b * SKL + t * 8 + i] != 0) ? 1 : 0;
        c += loc[i];
    }
    cnt[t] = c;
    __syncthreads();
    for (int off = 1; off < 256; off <<= 1) {
        int v = (t >= off) ? cnt[t - off] : 0;
        __syncthreads();
        cnt[t] += v;
        __syncthreads();
    }
    int pos = cnt[t] - c;
#pragma unroll
    for (int i = 0; i < 8; i++) g_rowmap[b * SKL + t * 8 + i] = -1;
    __syncthreads();
#pragma unroll
    for (int i = 0; i < 8; i++) {
        if (loc[i]) g_rowmap[b * SKL + pos++] = b * SKL + t * 8 + i;
    }
    if (t == 255) g_knum[b] = cnt[255];
}

// ===========================================================================
// Pipelined tensor-core GEMM over pre-split fp16 operands.
// C[M,1024] = gather(A)[M,1024] @ W^T + bias. CTA 128x128, BK=32,
// double-buffered smem, reg prefetch, 1 sync/stage. No conversions in loop.
// ===========================================================================
#define LDSROW 40
#define G_ARR  (128 * LDSROW)
#define G_BUF  (4 * G_ARR)
#define G_SMEM (2 * G_BUF * 2)      // 81920 bytes

__device__ __forceinline__ void g_ldg(
    const __half* Ah, const __half* Al,
    const __half* Wh, const __half* Wl,
    bool av, size_t aoff, size_t boff, int k0, uint4* rg)
{
    if (av) {
        rg[0] = *(const uint4*)(Ah + aoff + k0);
        rg[1] = *(const uint4*)(Ah + aoff + k0 + 8);
        rg[2] = *(const uint4*)(Al + aoff + k0);
        rg[3] = *(const uint4*)(Al + aoff + k0 + 8);
    } else {
        rg[0] = rg[1] = rg[2] = rg[3] = make_uint4(0u, 0u, 0u, 0u);
    }
    rg[4] = *(const uint4*)(Wh + boff + k0);
    rg[5] = *(const uint4*)(Wh + boff + k0 + 8);
    rg[6] = *(const uint4*)(Wl + boff + k0);
    rg[7] = *(const uint4*)(Wl + boff + k0 + 8);
}

__device__ __forceinline__ void g_sts(__half* buf, int lrow, int lcol,
                                      const uint4* rg)
{
    const int o = lrow * LDSROW + lcol;
    *(uint4*)&buf[o]                 = rg[0];
    *(uint4*)&buf[o + 8]             = rg[1];
    *(uint4*)&buf[G_ARR + o]         = rg[2];
    *(uint4*)&buf[G_ARR + o + 8]     = rg[3];
    *(uint4*)&buf[2 * G_ARR + o]     = rg[4];
    *(uint4*)&buf[2 * G_ARR + o + 8] = rg[5];
    *(uint4*)&buf[3 * G_ARR + o]     = rg[6];
    *(uint4*)&buf[3 * G_ARR + o + 8] = rg[7];
}

__global__ __launch_bounds__(256) void gemm_tc(
    const __half* __restrict__ Ah, const __half* __restrict__ Al,
    const __half* __restrict__ Wh, const __half* __restrict__ Wl,
    const float* __restrict__ bias,
    float* __restrict__ Cf, __half* __restrict__ Chi, __half* __restrict__ Clo,
    float oscale, const int* __restrict__ rowmap)
{
    extern __shared__ __half gsm[];

    const int tid  = threadIdx.x;
    const int w    = tid >> 5;
    const int lane = tid & 31;
    const int gid  = lane >> 2;
    const int tig  = lane & 3;
    const int bm   = blockIdx.y * 128;
    const int bn   = blockIdx.x * 128;
    const int wm = (w & 1) * 64;
    const int wn = (w >> 1) * 32;

    float acc[4][4][4];
#pragma unroll
    for (int i = 0; i < 4; i++)
#pragma unroll
        for (int j = 0; j < 4; j++)
#pragma unroll
            for (int k = 0; k < 4; k++) acc[i][j][k] = 0.f;

    const int lrow = tid >> 1;
    const int lcol = (tid & 1) * 16;
    int srow = bm + lrow;
    if (rowmap) srow = rowmap[srow];
    const bool avalid = (srow >= 0);
    const size_t aoff = (size_t)(avalid ? srow : 0) * 1024 + lcol;
    const size_t boff = (size_t)(bn + lrow) * 1024 + lcol;

    uint4 rg[8];
    g_ldg(Ah, Al, Wh, Wl, avalid, aoff, boff, 0, rg);
    g_sts(gsm, lrow, lcol, rg);

    for (int s = 0; s < 32; s++) {
        __syncthreads();
        if (s < 31) g_ldg(Ah, Al, Wh, Wl, avalid, aoff, boff, (s + 1) * 32, rg);

        __half* buf = gsm + (s & 1) * G_BUF;
        __half* sAhi = buf;
        __half* sAlo = buf + G_ARR;
        __half* sBhi = buf + 2 * G_ARR;
        __half* sBlo = buf + 3 * G_ARR;

#pragma unroll
        for (int ks = 0; ks < 2; ks++) {
            const int kb = ks * 16;
            uint32_t Ahi[4][4], Alo[4][4];
#pragma unroll
            for (int am = 0; am < 4; am++) {
                const int r0 = (wm + am * 16 + gid) * LDSROW + kb + tig * 2;
                const int r8 = r0 + 8 * LDSROW;
                Ahi[am][0] = *(const uint32_t*)&sAhi[r0];
                Ahi[am][1] = *(const uint32_t*)&sAhi[r8];
                Ahi[am][2] = *(const uint32_t*)&sAhi[r0 + 8];
                Ahi[am][3] = *(const uint32_t*)&sAhi[r8 + 8];
                Alo[am][0] = *(const uint32_t*)&sAlo[r0];
                Alo[am][1] = *(const uint32_t*)&sAlo[r8];
                Alo[am][2] = *(const uint32_t*)&sAlo[r0 + 8];
                Alo[am][3] = *(const uint32_t*)&sAlo[r8 + 8];
            }
            uint32_t Bhi[4][2], Blo[4][2];
#pragma unroll
            for (int an = 0; an < 4; an++) {
                const int r = (wn + an * 8 + gid) * LDSROW + kb + tig * 2;
                Bhi[an][0] = *(const uint32_t*)&sBhi[r];
                Bhi[an][1] = *(const uint32_t*)&sBhi[r + 8];
                Blo[an][0] = *(const uint32_t*)&sBlo[r];
                Blo[an][1] = *(const uint32_t*)&sBlo[r + 8];
            }
#pragma unroll
            for (int am = 0; am < 4; am++)
#pragma unroll
                for (int an = 0; an < 4; an++) {
                    mma16816(acc[am][an],
                             Ahi[am][0], Ahi[am][1], Ahi[am][2], Ahi[am][3],
                             Bhi[an][0], Bhi[an][1]);
                    mma16816(acc[am][an],
                             Ahi[am][0], Ahi[am][1], Ahi[am][2], Ahi[am][3],
                             Blo[an][0], Blo[an][1]);
                    mma16816(acc[am][an],
                             Alo[am][0], Alo[am][1], Alo[am][2], Alo[am][3],
                             Bhi[an][0], Bhi[an][1]);
                }
        }
        if (s < 31) g_sts(gsm + ((s + 1) & 1) * G_BUF, lrow, lcol, rg);
    }

    // Epilogue
#pragma unroll
    for (int am = 0; am < 4; am++) {
        const int row = bm + wm + am * 16 + gid;
        bool v0 = true, v1 = true;
        if (rowmap) {
            v0 = (rowmap[row] >= 0);
            v1 = (rowmap[row + 8] >= 0);
        }
#pragma unroll
        for (int an = 0; an < 4; an++) {
            const int col = bn + wn + an * 8 + tig * 2;
            const float b0 = bias[col], b1 = bias[col + 1];
            float o00 = v0 ? (acc[am][an][0] + b0) * oscale : 0.f;
            float o01 = v0 ? (acc[am][an][1] + b1) * oscale : 0.f;
            float o10 = v1 ? (acc[am][an][2] + b0) * oscale : 0.f;
            float o11 = v1 ? (acc[am][an][3] + b1) * oscale : 0.f;
            if (Chi) {
                __half h00 = __float2half_rn(o00), h01 = __float2half_rn(o01);
                __half h10 = __float2half_rn(o10), h11 = __float2half_rn(o11);
                *(uint32_t*)&Chi[(size_t)row * 1024 + col] =
                    pack_h2(__half2float(h00), __half2float(h01));
                *(uint32_t*)&Chi[(size_t)(row + 8) * 1024 + col] =
                    pack_h2(__half2float(h10), __half2float(h11));
                *(uint32_t*)&Clo[(size_t)row * 1024 + col] =
                    pack_h2(o00 - __half2float(h00), o01 - __half2float(h01));
                *(uint32_t*)&Clo[(size_t)(row + 8) * 1024 + col] =
                    pack_h2(o10 - __half2float(h10), o11 - __half2float(h11));
            } else {
                float2 f0 = {o00, o01}, f1 = {o10, o11};
                *(float2*)(Cf + (size_t)row * 1024 + col) = f0;
                *(float2*)(Cf + (size_t)(row + 8) * 1024 + col) = f1;
            }
        }
    }
}

// ===========================================================================
// Prep: V transpose + split -> Vt[b][h][d][key]
// ===========================================================================
__global__ __launch_bounds__(256) void prep_vt() {
    const int b = blockIdx.z, h = blockIdx.y, j0 = blockIdx.x * 64;
    const int nv  = g_knum[b];
    const int nkp = (nv + 63) & ~63;
    if (j0 >= nkp) return;
    __shared__ float tile[64][65];
    const int t = threadIdx.x;
#pragma unroll
    for (int p = 0; p < 4; p++) {
        const int r = p * 16 + (t >> 4);
        const int c = (t & 15) * 4;
        float4 v = *(const float4*)&g_Vc[((size_t)b * SKL + j0 + r) * 1024 + h * 64 + c];
        tile[c + 0][r] = v.x; tile[c + 1][r] = v.y;
        tile[c + 2][r] = v.z; tile[c + 3][r] = v.w;
    }
    __syncthreads();
    const int d = t >> 2, jg = (t & 3) * 16;
    ushort hi[16], lo[16];
#pragma unroll
    for (int i = 0; i < 16; i++) {
        float v = tile[d][jg + i];
        __half hb = __float2half_rn(v);
        __half lb = __float2half_rn(v - __half2float(hb));
        hi[i] = *(ushort*)&hb;
        lo[i] = *(ushort*)&lb;
    }
    const size_t base = (((size_t)(b * NH + h)) * 64 + d) * NKMAX + j0 + jg;
    *(uint4*)&g_Vthi[base]     = *(uint4*)hi;
    *(uint4*)&g_Vtlo[base]     = *(uint4*)lo;
    *(uint4*)&g_Vthi[base + 8] = *(uint4*)&hi[8];
    *(uint4*)&g_Vtlo[base + 8] = *(uint4*)&lo[8];
}

// ===========================================================================
// Pipelined tensor-core flash attention over compacted keys.
// ===========================================================================
#define FLDS  72
#define F_CH  (64 * FLDS)
#define F_BUF (4 * F_CH)
#define F_SMEM (2 * F_BUF * 2)      // 73728 bytes

__device__ __forceinline__ void f_ldg(int b, int h, int kt, int r, int c0,
                                      uint4* rg) {
    const size_t kb = ((size_t)b * SKL + kt + r) * 1024 + h * 64 + c0;
    rg[0] = *(const uint4*)&g_Khi[kb];
    rg[1] = *(const uint4*)&g_Khi[kb + 8];
    rg[2] = *(const uint4*)&g_Klo[kb];
    rg[3] = *(const uint4*)&g_Klo[kb + 8];
    const size_t vb = (((size_t)(b * NH + h)) * 64 + r) * NKMAX + kt + c0;
    rg[4] = *(const uint4*)&g_Vthi[vb];
    rg[5] = *(const uint4*)&g_Vthi[vb + 8];
    rg[6] = *(const uint4*)&g_Vtlo[vb];
    rg[7] = *(const uint4*)&g_Vtlo[vb + 8];
}

__device__ __forceinline__ void f_sts(__half* buf, int r, int c0,
                                      const uint4* rg) {
    const int o = r * FLDS + c0;
    *(uint4*)&buf[o]              = rg[0];
    *(uint4*)&buf[o + 8]          = rg[1];
    *(uint4*)&buf[F_CH + o]       = rg[2];
    *(uint4*)&buf[F_CH + o + 8]   = rg[3];
    *(uint4*)&buf[2 * F_CH + o]     = rg[4];
    *(uint4*)&buf[2 * F_CH + o + 8] = rg[5];
    *(uint4*)&buf[3 * F_CH + o]     = rg[6];
    *(uint4*)&buf[3 * F_CH + o + 8] = rg[7];
}

__global__ __launch_bounds__(256) void flash_tc() {
    extern __shared__ __half fsm[];

    const int b = blockIdx.z, h = blockIdx.y, q0 = blockIdx.x * 128;
    const int tid = threadIdx.x;
    const int w = tid >> 5, lane = tid & 31;
    const int gid = lane >> 2, tig = lane & 3;

    const int nv  = g_knum[b];
    const int nkp = (nv + 63) & ~63;

    // ---- Stage Q through buffer 0, pull fragments ----
    {
        const int r = tid >> 1, c0 = (tid & 1) * 32;
        const size_t gbase = ((size_t)b * SQL + q0 + r) * 1024 + h * 64 + c0;
        __half* qh = fsm + r * FLDS + c0;
        __half* ql = fsm + 128 * FLDS + r * FLDS + c0;
#pragma unroll
        for (int u = 0; u < 4; u++) {
            *(uint4*)&qh[u * 8] = *(const uint4*)&g_Qhi[gbase + u * 8];
            *(uint4*)&ql[u * 8] = *(const uint4*)&g_Qlo[gbase + u * 8];
        }
    }
    __syncthreads();

    uint32_t Qh[4][4], Ql[4][4];
    {
        const int qr = w * 16 + gid;
#pragma unroll
        for (int ks = 0; ks < 4; ks++) {
            const int base = qr * FLDS + ks * 16 + tig * 2;
            Qh[ks][0] = *(const uint32_t*)&fsm[base];
            Qh[ks][1] = *(const uint32_t*)&fsm[base + 8 * FLDS];
            Qh[ks][2] = *(const uint32_t*)&fsm[base + 8];
            Qh[ks][3] = *(const uint32_t*)&fsm[base + 8 * FLDS + 8];
            Ql[ks][0] = *(const uint32_t*)&fsm[128 * FLDS + base];
            Ql[ks][1] = *(const uint32_t*)&fsm[128 * FLDS + base + 8 * FLDS];
            Ql[ks][2] = *(const uint32_t*)&fsm[128 * FLDS + base + 8];
            Ql[ks][3] = *(const uint32_t*)&fsm[128 * FLDS + base + 8 * FLDS + 8];
        }
    }
    __syncthreads();

    float Oa[8][4];
#pragma unroll
    for (int i = 0; i < 8; i++)
#pragma unroll
        for (int j = 0; j < 4; j++) Oa[i][j] = 0.f;
    float m0 = -1e30f, m1 = -1e30f, l0 = 0.f, l1 = 0.f;

    const int lr = tid >> 2, lc0 = (tid & 3) * 16;
    uint4 rg[8];
    f_ldg(b, h, 0, lr, lc0, rg);
    f_sts(fsm, lr, lc0, rg);

    int par = 0;
    for (int kt = 0; kt < nkp; kt += 64, par ^= 1) {
        __syncthreads();
        const bool more = (kt + 64) < nkp;
        if (more) f_ldg(b, h, kt + 64, lr, lc0, rg);

        __half* buf = fsm + par * F_BUF;
        __half* sKh = buf;
        __half* sKl = buf + F_CH;
        __half* sVh = buf + 2 * F_CH;
        __half* sVl = buf + 3 * F_CH;

        // ---- S = Q K^T ----
        float S[8][4];
#pragma unroll
        for (int i = 0; i < 8; i++)
#pragma unroll
            for (int j = 0; j < 4; j++) S[i][j] = 0.f;

#pragma unroll
        for (int ks = 0; ks < 4; ks++) {
#pragma unroll
            for (int nt = 0; nt < 8; nt++) {
                const int kb = (nt * 8 + gid) * FLDS + ks * 16 + tig * 2;
                const uint32_t bh0 = *(const uint32_t*)&sKh[kb];
                const uint32_t bh1 = *(const uint32_t*)&sKh[kb + 8];
                const uint32_t bl0 = *(const uint32_t*)&sKl[kb];
                const uint32_t bl1 = *(const uint32_t*)&sKl[kb + 8];
                mma16816(S[nt], Qh[ks][0], Qh[ks][1], Qh[ks][2], Qh[ks][3], bh0, bh1);
                mma16816(S[nt], Qh[ks][0], Qh[ks][1], Qh[ks][2], Qh[ks][3], bl0, bl1);
                mma16816(S[nt], Ql[ks][0], Ql[ks][1], Ql[ks][2], Ql[ks][3], bh0, bh1);
            }
        }

        // ---- tail mask ----
        if (kt + 64 > nv) {
#pragma unroll
            for (int nt = 0; nt < 8; nt++) {
                const int col = kt + nt * 8 + tig * 2;
                if (col >= nv)     { S[nt][0] = -1e30f; S[nt][2] = -1e30f; }
                if (col + 1 >= nv) { S[nt][1] = -1e30f; S[nt][3] = -1e30f; }
            }
        }

        // ---- online softmax ----
        float mx0 = -1e30f, mx1 = -1e30f;
#pragma unroll
        for (int nt = 0; nt < 8; nt++) {
            mx0 = fmaxf(mx0, fmaxf(S[nt][0], S[nt][1]));
            mx1 = fmaxf(mx1, fmaxf(S[nt][2], S[nt][3]));
        }
        mx0 = fmaxf(mx0, __shfl_xor_sync(0xffffffffu, mx0, 1));
        mx0 = fmaxf(mx0, __shfl_xor_sync(0xffffffffu, mx0, 2));
        mx1 = fmaxf(mx1, __shfl_xor_sync(0xffffffffu, mx1, 1));
        mx1 = fmaxf(mx1, __shfl_xor_sync(0xffffffffu, mx1, 2));

        const float mn0 = fmaxf(m0, mx0), mn1 = fmaxf(m1, mx1);
        const float corr0 = __expf(m0 - mn0), corr1 = __expf(m1 - mn1);
        m0 = mn0; m1 = mn1;

        float sum0 = 0.f, sum1 = 0.f;
        uint32_t Ph[4][4], Pl[4][4];
#pragma unroll
        for (int nt = 0; nt < 8; nt++) {
            const float p0 = __expf(S[nt][0] - m0);
            const float p1 = __expf(S[nt][1] - m0);
            const float p2 = __expf(S[nt][2] - m1);
            const float p3 = __expf(S[nt][3] - m1);
            sum0 += p0 + p1; sum1 += p2 + p3;
            __half h0 = __float2half_rn(p0), h1 = __float2half_rn(p1);
            __half h2 = __float2half_rn(p2), h3 = __float2half_rn(p3);
            const float f0 = __half2float(h0), f1 = __half2float(h1);
            const float f2 = __half2float(h2), f3 = __half2float(h3);
            const uint32_t hi01 = pack_h2(f0, f1);
            const uint32_t hi23 = pack_h2(f2, f3);
            const uint32_t lo01 = pack_h2(p0 - f0, p1 - f1);
            const uint32_t lo23 = pack_h2(p2 - f2, p3 - f3);
            const int ks = nt >> 1;
            if ((nt & 1) == 0) {
                Ph[ks][0] = hi01; Ph[ks][1] = hi23;
                Pl[ks][0] = lo01; Pl[ks][1] = lo23;
            } else {
                Ph[ks][2] = hi01; Ph[ks][3] = hi23;
                Pl[ks][2] = lo01; Pl[ks][3] = lo23;
            }
        }
        sum0 += __shfl_xor_sync(0xffffffffu, sum0, 1);
        sum0 += __shfl_xor_sync(0xffffffffu, sum0, 2);
        sum1 += __shfl_xor_sync(0xffffffffu, sum1, 1);
        sum1 += __shfl_xor_sync(0xffffffffu, sum1, 2);
        l0 = l0 * corr0 + sum0;
        l1 = l1 * corr1 + sum1;

#pragma unroll
        for (int nt = 0; nt < 8; nt++) {
            Oa[nt][0] *= corr0; Oa[nt][1] *= corr0;
            Oa[nt][2] *= corr1; Oa[nt][3] *= corr1;
        }

        // ---- O += P V ----
#pragma unroll
        for (int ks = 0; ks < 4; ks++) {
#pragma unroll
            for (int nt = 0; nt < 8; nt++) {
                const int vb = (nt * 8 + gid) * FLDS + ks * 16 + tig * 2;
                const uint32_t bh0 = *(const uint32_t*)&sVh[vb];
                const uint32_t bh1 = *(const uint32_t*)&sVh[vb + 8];
                const uint32_t bl0 = *(const uint32_t*)&sVl[vb];
                const uint32_t bl1 = *(const uint32_t*)&sVl[vb + 8];
                mma16816(Oa[nt], Ph[ks][0], Ph[ks][1], Ph[ks][2], Ph[ks][3], bh0, bh1);
                mma16816(Oa[nt], Ph[ks][0], Ph[ks][1], Ph[ks][2], Ph[ks][3], bl0, bl1);
                mma16816(Oa[nt], Pl[ks][0], Pl[ks][1], Pl[ks][2], Pl[ks][3], bh0, bh1);
            }
        }

        if (more) f_sts(fsm + (par ^ 1) * F_BUF, lr, lc0, rg);
    }

    // ---- epilogue: write split fp16 attention output ----
    const float inv0 = 1.f / l0, inv1 = 1.f / l1;
    const int row0 = q0 + w * 16 + gid;
#pragma unroll
    for (int nt = 0; nt < 8; nt++) {
        const int col = h * 64 + nt * 8 + tig * 2;
        const float o00 = Oa[nt][0] * inv0, o01 = Oa[nt][1] * inv0;
        const float o10 = Oa[nt][2] * inv1, o11 = Oa[nt][3] * inv1;
        __half h00 = __float2half_rn(o00), h01 = __float2half_rn(o01);
        __half h10 = __float2half_rn(o10), h11 = __float2half_rn(o11);
        const size_t i0 = ((size_t)b * SQL + row0) * 1024 + col;
        const size_t i1 = ((size_t)b * SQL + row0 + 8) * 1024 + col;
        *(uint32_t*)&g_AOhi[i0] = pack_h2(__half2float(h00), __half2float(h01));
        *(uint32_t*)&g_AOhi[i1] = pack_h2(__half2float(h10), __half2float(h11));
        *(uint32_t*)&g_AOlo[i0] = pack_h2(o00 - __half2float(h00), o01 - __half2float(h01));
        *(uint32_t*)&g_AOlo[i1] = pack_h2(o10 - __half2float(h10), o11 - __half2float(h11));
    }
}

// ---------------------------------------------------------------------------
extern "C" void kernel_launch(void* const* d_in, const int* in_sizes, int n_in,
                              void* d_out, int out_size)
{
    const float* query = (const float*)d_in[0];
    const float* key   = (const float*)d_in[1];
    const float* value = (const float*)d_in[2];
    const int*   kpm   = (const int*)  d_in[3];
    const float* Wq    = (const float*)d_in[4];
    const float* bq    = (const float*)d_in[5];
    const float* Wk    = (const float*)d_in[6];
    const float* bk    = (const float*)d_in[7];
    const float* Wv    = (const float*)d_in[8];
    const float* bv    = (const float*)d_in[9];
    const float* Wo    = (const float*)d_in[10];
    const float* bo    = (const float*)d_in[11];
    float* out = (float*)d_out;

    __half *qsh, *qsl, *ksh, *ksl, *vsh, *vsl;
    __half *wqh, *wql, *wkh, *wkl, *wvh, *wvl, *woh, *wol;
    __half *QhiP, *QloP, *KhiP, *KloP, *AOhiP, *AOloP;
    float *VcP;
    int *rmP;
    cudaGetSymbolAddress((void**)&qsh, g_qsh);
    cudaGetSymbolAddress((void**)&qsl, g_qsl);
    cudaGetSymbolAddress((void**)&ksh, g_ksh);
    cudaGetSymbolAddress((void**)&ksl, g_ksl);
    cudaGetSymbolAddress((void**)&vsh, g_vsh);
    cudaGetSymbolAddress((void**)&vsl, g_vsl);
    cudaGetSymbolAddress((void**)&wqh, g_wqh);
    cudaGetSymbolAddress((void**)&wql, g_wql);
    cudaGetSymbolAddress((void**)&wkh, g_wkh);
    cudaGetSymbolAddress((void**)&wkl, g_wkl);
    cudaGetSymbolAddress((void**)&wvh, g_wvh);
    cudaGetSymbolAddress((void**)&wvl, g_wvl);
    cudaGetSymbolAddress((void**)&woh, g_woh);
    cudaGetSymbolAddress((void**)&wol, g_wol);
    cudaGetSymbolAddress((void**)&QhiP, g_Qhi);
    cudaGetSymbolAddress((void**)&QloP, g_Qlo);
    cudaGetSymbolAddress((void**)&KhiP, g_Khi);
    cudaGetSymbolAddress((void**)&KloP, g_Klo);
    cudaGetSymbolAddress((void**)&AOhiP, g_AOhi);
    cudaGetSymbolAddress((void**)&AOloP, g_AOlo);
    cudaGetSymbolAddress((void**)&VcP, g_Vc);
    cudaGetSymbolAddress((void**)&rmP, g_rowmap);

    cudaFuncSetAttribute(gemm_tc, cudaFuncAttributeMaxDynamicSharedMemorySize,
                         G_SMEM);
    cudaFuncSetAttribute(flash_tc, cudaFuncAttributeMaxDynamicSharedMemorySize,
                         F_SMEM);

    scan_mask<<<BB, 256>>>(kpm);

    const int gin = (int)(NIN / 1024);   // 8192 blocks (4 f32/thread)
    const int gw  = (int)(NW  / 1024);   // 1024 blocks
    split_src<<<gin, 256>>>(query, qsh, qsl);
    split_src<<<gin, 256>>>(key,   ksh, ksl);
    split_src<<<gin, 256>>>(value, vsh, vsl);
    split_src<<<gw, 256>>>(Wq, wqh, wql);
    split_src<<<gw, 256>>>(Wk, wkh, wkl);
    split_src<<<gw, 256>>>(Wv, wvh, wvl);
    split_src<<<gw, 256>>>(Wo, woh, wol);

    dim3 gGemm(DMODEL / 128, (BB * SQL) / 128);   // (8, 64)

    // Q: split output, softmax scale folded
    gemm_tc<<<gGemm, 256, G_SMEM>>>(qsh, qsl, wqh, wql, bq,
                                    nullptr, QhiP, QloP, 0.125f, nullptr);
    // K: gather + split output
    gemm_tc<<<gGemm, 256, G_SMEM>>>(ksh, ksl, wkh, wkl, bk,
                                    nullptr, KhiP, KloP, 1.0f, rmP);
    // V: gather, f32 compacted output
    gemm_tc<<<gGemm, 256, G_SMEM>>>(vsh, vsl, wvh, wvl, bv,
                                    VcP, nullptr, nullptr, 1.0f, rmP);

    prep_vt<<<dim3(SKL / 64, NH, BB), 256>>>();

    flash_tc<<<dim3(SQL / 128, NH, BB), 256, F_SMEM>>>();

    // O projection -> final f32 output
    gemm_tc<<<gGemm, 256, G_SMEM>>>(AOhiP, AOloP, woh, wol, bo,
                                    out, nullptr, nullptr, 1.0f, nullptr);
}

// round 7
// speedup vs baseline: 5.8417x; 1.1501x over previous
#include <cuda_runtime.h>
#include <cuda_fp16.h>
#include <cstdint>

#define BB     4
#define SQL    2048
#define SKL    2048
#define DMODEL 1024
#define NH     16
#define HDIM   64
#define NKMAX  2048

#define NIN  ((size_t)BB * SQL * DMODEL)
#define NW   ((size_t)DMODEL * DMODEL)

// Pre-split sources (fp16 hi/lo)
__device__ __half g_qsh[NIN], g_qsl[NIN];
__device__ __half g_ksh[NIN], g_ksl[NIN];
__device__ __half g_vsh[NIN], g_vsl[NIN];
__device__ __half g_wqh[NW],  g_wql[NW];
__device__ __half g_wkh[NW],  g_wkl[NW];
__device__ __half g_wvh[NW],  g_wvl[NW];
__device__ __half g_woh[NW],  g_wol[NW];
// Projected tensors
__device__ __half g_Qhi[NIN], g_Qlo[NIN];
__device__ __half g_Khi[NIN], g_Klo[NIN];
__device__ float  g_Vc [NIN];
__device__ __half g_Vthi[(size_t)BB * NH * HDIM * NKMAX];
__device__ __half g_Vtlo[(size_t)BB * NH * HDIM * NKMAX];
__device__ __half g_AOhi[NIN], g_AOlo[NIN];
__device__ int g_rowmap[BB * SKL];
__device__ int g_knum[BB];

// ===========================================================================
// PTX helpers
// ===========================================================================
__device__ __forceinline__ void mma16816(float c[4],
                                         uint32_t a0, uint32_t a1,
                                         uint32_t a2, uint32_t a3,
                                         uint32_t b0, uint32_t b1) {
    asm volatile(
        "mma.sync.aligned.m16n8k16.row.col.f32.f16.f16.f32 "
        "{%0,%1,%2,%3}, {%4,%5,%6,%7}, {%8,%9}, {%0,%1,%2,%3};"
        : "+f"(c[0]), "+f"(c[1]), "+f"(c[2]), "+f"(c[3])
        : "r"(a0), "r"(a1), "r"(a2), "r"(a3), "r"(b0), "r"(b1));
}

__device__ __forceinline__ void ldm_x4(uint32_t* r, uint32_t saddr) {
    asm volatile(
        "ldmatrix.sync.aligned.m8n8.x4.shared.b16 {%0,%1,%2,%3}, [%4];"
        : "=r"(r[0]), "=r"(r[1]), "=r"(r[2]), "=r"(r[3]) : "r"(saddr));
}

__device__ __forceinline__ uint32_t s2u(const void* p) {
    return (uint32_t)__cvta_generic_to_shared(p);
}

__device__ __forceinline__ uint32_t pack_h2(float a, float b) {
    __half2 h = __floats2half2_rn(a, b);
    return *(uint32_t*)&h;
}

__device__ __forceinline__ void split_pack4(float4 v, uint2& h, uint2& l) {
    __half hx = __float2half_rn(v.x);
    __half hy = __float2half_rn(v.y);
    __half hz = __float2half_rn(v.z);
    __half hw = __float2half_rn(v.w);
    h.x = pack_h2(__half2float(hx), __half2float(hy));
    h.y = pack_h2(__half2float(hz), __half2float(hw));
    l.x = pack_h2(v.x - __half2float(hx), v.y - __half2float(hy));
    l.y = pack_h2(v.z - __half2float(hz), v.w - __half2float(hw));
}

// ===========================================================================
// Preps
// ===========================================================================
__global__ __launch_bounds__(256) void split_src(
    const float* __restrict__ src, __half* __restrict__ hi,
    __half* __restrict__ lo)
{
    const size_t i = (size_t)blockIdx.x * 256 + threadIdx.x;
    float4 v = *(const float4*)(src + i * 4);
    uint2 h, l;
    split_pack4(v, h, l);
    *(uint2*)(hi + i * 4) = h;
    *(uint2*)(lo + i * 4) = l;
}

__global__ __launch_bounds__(256) void scan_mask(const int* __restrict__ kpm) {
    const int b = blockIdx.x, t = threadIdx.x;
    __shared__ int cnt[256];
    int loc[8], c = 0;
#pragma unroll
    for (int i = 0; i < 8; i++) {
        loc[i] = (kpm[b * SKL + t * 8 + i] != 0) ? 1 : 0;
        c += loc[i];
    }
    cnt[t] = c;
    __syncthreads();
    for (int off = 1; off < 256; off <<= 1) {
        int v = (t >= off) ? cnt[t - off] : 0;
        __syncthreads();
        cnt[t] += v;
        __syncthreads();
    }
    int pos = cnt[t] - c;
#pragma unroll
    for (int i = 0; i < 8; i++) g_rowmap[b * SKL + t * 8 + i] = -1;
    __syncthreads();
#pragma unroll
    for (int i = 0; i < 8; i++) {
        if (loc[i]) g_rowmap[b * SKL + pos++] = b * SKL + t * 8 + i;
    }
    if (t == 255) g_knum[b] = cnt[255];
}

// ===========================================================================
// GEMM body (ldmatrix fragments, double-buffered, reg prefetch)
// ===========================================================================
#define LDSROW 40
#define G_ARR  (128 * LDSROW)
#define G_BUF  (4 * G_ARR)
#define G_SMEM (2 * G_BUF * 2)

__device__ __forceinline__ void g_ldg(
    const __half* Ah, const __half* Al,
    const __half* Wh, const __half* Wl,
    bool av, size_t aoff, size_t boff, int k0, uint4* rg)
{
    if (av) {
        rg[0] = *(const uint4*)(Ah + aoff + k0);
        rg[1] = *(const uint4*)(Ah + aoff + k0 + 8);
        rg[2] = *(const uint4*)(Al + aoff + k0);
        rg[3] = *(const uint4*)(Al + aoff + k0 + 8);
    } else {
        rg[0] = rg[1] = rg[2] = rg[3] = make_uint4(0u, 0u, 0u, 0u);
    }
    rg[4] = *(const uint4*)(Wh + boff + k0);
    rg[5] = *(const uint4*)(Wh + boff + k0 + 8);
    rg[6] = *(const uint4*)(Wl + boff + k0);
    rg[7] = *(const uint4*)(Wl + boff + k0 + 8);
}

__device__ __forceinline__ void g_sts(__half* buf, int lrow, int lcol,
                                      const uint4* rg)
{
    const int o = lrow * LDSROW + lcol;
    *(uint4*)&buf[o]                 = rg[0];
    *(uint4*)&buf[o + 8]             = rg[1];
    *(uint4*)&buf[G_ARR + o]         = rg[2];
    *(uint4*)&buf[G_ARR + o + 8]     = rg[3];
    *(uint4*)&buf[2 * G_ARR + o]     = rg[4];
    *(uint4*)&buf[2 * G_ARR + o + 8] = rg[5];
    *(uint4*)&buf[3 * G_ARR + o]     = rg[6];
    *(uint4*)&buf[3 * G_ARR + o + 8] = rg[7];
}

__device__ __forceinline__ void gemm_body(
    const __half* __restrict__ Ah, const __half* __restrict__ Al,
    const __half* __restrict__ Wh, const __half* __restrict__ Wl,
    const float* __restrict__ bias,
    float* __restrict__ Cf, __half* __restrict__ Chi, __half* __restrict__ Clo,
    float oscale, const int* __restrict__ rowmap, __half* gsm)
{
    const int tid  = threadIdx.x;
    const int w    = tid >> 5;
    const int lane = tid & 31;
    const int gid  = lane >> 2;
    const int tig  = lane & 3;
    const int bm   = blockIdx.y * 128;
    const int bn   = blockIdx.x * 128;
    const int wm = (w & 1) * 64;
    const int wn = (w >> 1) * 32;

    float acc[4][4][4];
#pragma unroll
    for (int i = 0; i < 4; i++)
#pragma unroll
        for (int j = 0; j < 4; j++)
#pragma unroll
            for (int k = 0; k < 4; k++) acc[i][j][k] = 0.f;

    const int lrow = tid >> 1;
    const int lcol = (tid & 1) * 16;
    int srow = bm + lrow;
    if (rowmap) srow = rowmap[srow];
    const bool avalid = (srow >= 0);
    const size_t aoff = (size_t)(avalid ? srow : 0) * 1024 + lcol;
    const size_t boff = (size_t)(bn + lrow) * 1024 + lcol;

    // ldmatrix per-lane element offsets
    const uint32_t sb = s2u(gsm);
    const int aoffL = (wm + (lane & 15)) * LDSROW + (lane >> 4) * 8;
    const int boffL = (wn + ((lane & 7) | ((lane >> 1) & 8))) * LDSROW
                      + ((lane >> 3) & 1) * 8;

    uint4 rg[8];
    g_ldg(Ah, Al, Wh, Wl, avalid, aoff, boff, 0, rg);
    g_sts(gsm, lrow, lcol, rg);

    for (int s = 0; s < 32; s++) {
        __syncthreads();
        if (s < 31) g_ldg(Ah, Al, Wh, Wl, avalid, aoff, boff, (s + 1) * 32, rg);

        const uint32_t base = sb + ((s & 1) ? (uint32_t)(G_BUF * 2) : 0u);

#pragma unroll
        for (int ks = 0; ks < 2; ks++) {
            const int kb = ks * 16;
            uint32_t Ahi[4][4], Alo[4][4];
#pragma unroll
            for (int am = 0; am < 4; am++) {
                const uint32_t ad = (uint32_t)((aoffL + am * 16 * LDSROW + kb) * 2);
                ldm_x4(Ahi[am], base + ad);
                ldm_x4(Alo[am], base + (uint32_t)(G_ARR * 2) + ad);
            }
            uint32_t Bh[8], Bl[8];
#pragma unroll
            for (int pr = 0; pr < 2; pr++) {
                const uint32_t bd = (uint32_t)((boffL + pr * 16 * LDSROW + kb) * 2);
                ldm_x4(&Bh[pr * 4], base + (uint32_t)(2 * G_ARR * 2) + bd);
                ldm_x4(&Bl[pr * 4], base + (uint32_t)(3 * G_ARR * 2) + bd);
            }
#pragma unroll
            for (int am = 0; am < 4; am++)
#pragma unroll
                for (int an = 0; an < 4; an++) {
                    mma16816(acc[am][an],
                             Ahi[am][0], Ahi[am][1], Ahi[am][2], Ahi[am][3],
                             Bh[an * 2], Bh[an * 2 + 1]);
                    mma16816(acc[am][an],
                             Ahi[am][0], Ahi[am][1], Ahi[am][2], Ahi[am][3],
                             Bl[an * 2], Bl[an * 2 + 1]);
                    mma16816(acc[am][an],
                             Alo[am][0], Alo[am][1], Alo[am][2], Alo[am][3],
                             Bh[an * 2], Bh[an * 2 + 1]);
                }
        }
        if (s < 31) g_sts(gsm + ((s + 1) & 1) * G_BUF, lrow, lcol, rg);
    }

    // Epilogue
#pragma unroll
    for (int am = 0; am < 4; am++) {
        const int row = bm + wm + am * 16 + gid;
        bool v0 = true, v1 = true;
        if (rowmap) {
            v0 = (rowmap[row] >= 0);
            v1 = (rowmap[row + 8] >= 0);
        }
#pragma unroll
        for (int an = 0; an < 4; an++) {
            const int col = bn + wn + an * 8 + tig * 2;
            const float b0 = bias[col], b1 = bias[col + 1];
            float o00 = v0 ? (acc[am][an][0] + b0) * oscale : 0.f;
            float o01 = v0 ? (acc[am][an][1] + b1) * oscale : 0.f;
            float o10 = v1 ? (acc[am][an][2] + b0) * oscale : 0.f;
            float o11 = v1 ? (acc[am][an][3] + b1) * oscale : 0.f;
            if (Chi) {
                __half h00 = __float2half_rn(o00), h01 = __float2half_rn(o01);
                __half h10 = __float2half_rn(o10), h11 = __float2half_rn(o11);
                *(uint32_t*)&Chi[(size_t)row * 1024 + col] =
                    pack_h2(__half2float(h00), __half2float(h01));
                *(uint32_t*)&Chi[(size_t)(row + 8) * 1024 + col] =
                    pack_h2(__half2float(h10), __half2float(h11));
                *(uint32_t*)&Clo[(size_t)row * 1024 + col] =
                    pack_h2(o00 - __half2float(h00), o01 - __half2float(h01));
                *(uint32_t*)&Clo[(size_t)(row + 8) * 1024 + col] =
                    pack_h2(o10 - __half2float(h10), o11 - __half2float(h11));
            } else {
                float2 f0 = {o00, o01}, f1 = {o10, o11};
                *(float2*)(Cf + (size_t)row * 1024 + col) = f0;
                *(float2*)(Cf + (size_t)(row + 8) * 1024 + col) = f1;
            }
        }
    }
}

// Fused Q/K/V projections: blockIdx.z selects operand set.
__global__ __launch_bounds__(256) void qkv_gemm(
    const float* __restrict__ bq, const float* __restrict__ bk,
    const float* __restrict__ bv)
{
    extern __shared__ __half gsm[];
    if (blockIdx.z == 0) {
        gemm_body(g_qsh, g_qsl, g_wqh, g_wql, bq,
                  nullptr, g_Qhi, g_Qlo, 0.125f, nullptr, gsm);
    } else if (blockIdx.z == 1) {
        gemm_body(g_ksh, g_ksl, g_wkh, g_wkl, bk,
                  nullptr, g_Khi, g_Klo, 1.0f, g_rowmap, gsm);
    } else {
        gemm_body(g_vsh, g_vsl, g_wvh, g_wvl, bv,
                  g_Vc, nullptr, nullptr, 1.0f, g_rowmap, gsm);
    }
}

// O projection
__global__ __launch_bounds__(256) void o_gemm(
    const float* __restrict__ bo, float* __restrict__ out)
{
    extern __shared__ __half gsm[];
    gemm_body(g_AOhi, g_AOlo, g_woh, g_wol, bo,
              out, nullptr, nullptr, 1.0f, nullptr, gsm);
}

// ===========================================================================
// Prep: V transpose + split -> Vt[b][h][d][key]
// ===========================================================================
__global__ __launch_bounds__(256) void prep_vt() {
    const int b = blockIdx.z, h = blockIdx.y, j0 = blockIdx.x * 64;
    const int nv  = g_knum[b];
    const int nkp = (nv + 63) & ~63;
    if (j0 >= nkp) return;
    __shared__ float tile[64][65];
    const int t = threadIdx.x;
#pragma unroll
    for (int p = 0; p < 4; p++) {
        const int r = p * 16 + (t >> 4);
        const int c = (t & 15) * 4;
        float4 v = *(const float4*)&g_Vc[((size_t)b * SKL + j0 + r) * 1024 + h * 64 + c];
        tile[c + 0][r] = v.x; tile[c + 1][r] = v.y;
        tile[c + 2][r] = v.z; tile[c + 3][r] = v.w;
    }
    __syncthreads();
    const int d = t >> 2, jg = (t & 3) * 16;
    ushort hi[16], lo[16];
#pragma unroll
    for (int i = 0; i < 16; i++) {
        float v = tile[d][jg + i];
        __half hb = __float2half_rn(v);
        __half lb = __float2half_rn(v - __half2float(hb));
        hi[i] = *(ushort*)&hb;
        lo[i] = *(ushort*)&lb;
    }
    const size_t base = (((size_t)(b * NH + h)) * 64 + d) * NKMAX + j0 + jg;
    *(uint4*)&g_Vthi[base]     = *(uint4*)hi;
    *(uint4*)&g_Vtlo[base]     = *(uint4*)lo;
    *(uint4*)&g_Vthi[base + 8] = *(uint4*)&hi[8];
    *(uint4*)&g_Vtlo[base + 8] = *(uint4*)&lo[8];
}

// ===========================================================================
// Flash attention (ldmatrix fragments, double-buffered)
// ===========================================================================
#define FLDS  72
#define F_CH  (64 * FLDS)
#define F_BUF (4 * F_CH)
#define F_SMEM (2 * F_BUF * 2)

__device__ __forceinline__ void f_ldg(int b, int h, int kt, int r, int c0,
                                      uint4* rg) {
    const size_t kb = ((size_t)b * SKL + kt + r) * 1024 + h * 64 + c0;
    rg[0] = *(const uint4*)&g_Khi[kb];
    rg[1] = *(const uint4*)&g_Khi[kb + 8];
    rg[2] = *(const uint4*)&g_Klo[kb];
    rg[3] = *(const uint4*)&g_Klo[kb + 8];
    const size_t vb = (((size_t)(b * NH + h)) * 64 + r) * NKMAX + kt + c0;
    rg[4] = *(const uint4*)&g_Vthi[vb];
    rg[5] = *(const uint4*)&g_Vthi[vb + 8];
    rg[6] = *(const uint4*)&g_Vtlo[vb];
    rg[7] = *(const uint4*)&g_Vtlo[vb + 8];
}

__device__ __forceinline__ void f_sts(__half* buf, int r, int c0,
                                      const uint4* rg) {
    const int o = r * FLDS + c0;
    *(uint4*)&buf[o]                = rg[0];
    *(uint4*)&buf[o + 8]            = rg[1];
    *(uint4*)&buf[F_CH + o]         = rg[2];
    *(uint4*)&buf[F_CH + o + 8]     = rg[3];
    *(uint4*)&buf[2 * F_CH + o]     = rg[4];
    *(uint4*)&buf[2 * F_CH + o + 8] = rg[5];
    *(uint4*)&buf[3 * F_CH + o]     = rg[6];
    *(uint4*)&buf[3 * F_CH + o + 8] = rg[7];
}

__global__ __launch_bounds__(256) void flash_tc() {
    extern __shared__ __half fsm[];

    const int b = blockIdx.z, h = blockIdx.y, q0 = blockIdx.x * 128;
    const int tid = threadIdx.x;
    const int w = tid >> 5, lane = tid & 31;
    const int gid = lane >> 2, tig = lane & 3;

    const int nv  = g_knum[b];
    const int nkp = (nv + 63) & ~63;

    // ---- Stage Q through buffer 0, pull fragments ----
    {
        const int r = tid >> 1, c0 = (tid & 1) * 32;
        const size_t gbase = ((size_t)b * SQL + q0 + r) * 1024 + h * 64 + c0;
        __half* qh = fsm + r * FLDS + c0;
        __half* ql = fsm + 128 * FLDS + r * FLDS + c0;
#pragma unroll
        for (int u = 0; u < 4; u++) {
            *(uint4*)&qh[u * 8] = *(const uint4*)&g_Qhi[gbase + u * 8];
            *(uint4*)&ql[u * 8] = *(const uint4*)&g_Qlo[gbase + u * 8];
        }
    }
    __syncthreads();

    const uint32_t fb = s2u(fsm);
    uint32_t Qh[4][4], Ql[4][4];
    {
        const int qoffL = (w * 16 + (lane & 15)) * FLDS + (lane >> 4) * 8;
#pragma unroll
        for (int ks = 0; ks < 4; ks++) {
            const uint32_t ad = (uint32_t)((qoffL + ks * 16) * 2);
            ldm_x4(Qh[ks], fb + ad);
            ldm_x4(Ql[ks], fb + (uint32_t)(128 * FLDS * 2) + ad);
        }
    }
    __syncthreads();

    float Oa[8][4];
#pragma unroll
    for (int i = 0; i < 8; i++)
#pragma unroll
        for (int j = 0; j < 4; j++) Oa[i][j] = 0.f;
    float m0 = -1e30f, m1 = -1e30f, l0 = 0.f, l1 = 0.f;

    const int lr = tid >> 2, lc0 = (tid & 3) * 16;
    const int foffL = ((lane & 7) | ((lane >> 1) & 8)) * FLDS
                      + ((lane >> 3) & 1) * 8;
    uint4 rg[8];
    f_ldg(b, h, 0, lr, lc0, rg);
    f_sts(fsm, lr, lc0, rg);

    int par = 0;
    for (int kt = 0; kt < nkp; kt += 64, par ^= 1) {
        __syncthreads();
        const bool more = (kt + 64) < nkp;
        if (more) f_ldg(b, h, kt + 64, lr, lc0, rg);

        const uint32_t base = fb + (uint32_t)(par * F_BUF * 2);

        // ---- S = Q K^T ----
        float S[8][4];
#pragma unroll
        for (int i = 0; i < 8; i++)
#pragma unroll
            for (int j = 0; j < 4; j++) S[i][j] = 0.f;

#pragma unroll
        for (int ks = 0; ks < 4; ks++) {
            const int kb = ks * 16;
#pragma unroll
            for (int pr = 0; pr < 4; pr++) {
                const uint32_t bd = (uint32_t)((foffL + pr * 16 * FLDS + kb) * 2);
                uint32_t kh[4], kl[4];
                ldm_x4(kh, base + bd);
                ldm_x4(kl, base + (uint32_t)(F_CH * 2) + bd);
#pragma unroll
                for (int t2 = 0; t2 < 2; t2++) {
                    const int nt = pr * 2 + t2;
                    mma16816(S[nt], Qh[ks][0], Qh[ks][1], Qh[ks][2], Qh[ks][3],
                             kh[t2 * 2], kh[t2 * 2 + 1]);
                    mma16816(S[nt], Qh[ks][0], Qh[ks][1], Qh[ks][2], Qh[ks][3],
                             kl[t2 * 2], kl[t2 * 2 + 1]);
                    mma16816(S[nt], Ql[ks][0], Ql[ks][1], Ql[ks][2], Ql[ks][3],
                             kh[t2 * 2], kh[t2 * 2 + 1]);
                }
            }
        }

        // ---- tail mask ----
        if (kt + 64 > nv) {
#pragma unroll
            for (int nt = 0; nt < 8; nt++) {
                const int col = kt + nt * 8 + tig * 2;
                if (col >= nv)     { S[nt][0] = -1e30f; S[nt][2] = -1e30f; }
                if (col + 1 >= nv) { S[nt][1] = -1e30f; S[nt][3] = -1e30f; }
            }
        }

        // ---- online softmax ----
        float mx0 = -1e30f, mx1 = -1e30f;
#pragma unroll
        for (int nt = 0; nt < 8; nt++) {
            mx0 = fmaxf(mx0, fmaxf(S[nt][0], S[nt][1]));
            mx1 = fmaxf(mx1, fmaxf(S[nt][2], S[nt][3]));
        }
        mx0 = fmaxf(mx0, __shfl_xor_sync(0xffffffffu, mx0, 1));
        mx0 = fmaxf(mx0, __shfl_xor_sync(0xffffffffu, mx0, 2));
        mx1 = fmaxf(mx1, __shfl_xor_sync(0xffffffffu, mx1, 1));
        mx1 = fmaxf(mx1, __shfl_xor_sync(0xffffffffu, mx1, 2));

        const float mn0 = fmaxf(m0, mx0), mn1 = fmaxf(m1, mx1);
        const float corr0 = __expf(m0 - mn0), corr1 = __expf(m1 - mn1);
        m0 = mn0; m1 = mn1;

        float sum0 = 0.f, sum1 = 0.f;
        uint32_t Ph[4][4], Pl[4][4];
#pragma unroll
        for (int nt = 0; nt < 8; nt++) {
            const float p0 = __expf(S[nt][0] - m0);
            const float p1 = __expf(S[nt][1] - m0);
            const float p2 = __expf(S[nt][2] - m1);
            const float p3 = __expf(S[nt][3] - m1);
            sum0 += p0 + p1; sum1 += p2 + p3;
            __half h0 = __float2half_rn(p0), h1 = __float2half_rn(p1);
            __half h2 = __float2half_rn(p2), h3 = __float2half_rn(p3);
            const float f0 = __half2float(h0), f1 = __half2float(h1);
            const float f2 = __half2float(h2), f3 = __half2float(h3);
            const uint32_t hi01 = pack_h2(f0, f1);
            const uint32_t hi23 = pack_h2(f2, f3);
            const uint32_t lo01 = pack_h2(p0 - f0, p1 - f1);
            const uint32_t lo23 = pack_h2(p2 - f2, p3 - f3);
            const int ks = nt >> 1;
            if ((nt & 1) == 0) {
                Ph[ks][0] = hi01; Ph[ks][1] = hi23;
                Pl[ks][0] = lo01; Pl[ks][1] = lo23;
            } else {
                Ph[ks][2] = hi01; Ph[ks][3] = hi23;
                Pl[ks][2] = lo01; Pl[ks][3] = lo23;
            }
        }
        sum0 += __shfl_xor_sync(0xffffffffu, sum0, 1);
        sum0 += __shfl_xor_sync(0xffffffffu, sum0, 2);
        sum1 += __shfl_xor_sync(0xffffffffu, sum1, 1);
        sum1 += __shfl_xor_sync(0xffffffffu, sum1, 2);
        l0 = l0 * corr0 + sum0;
        l1 = l1 * corr1 + sum1;

#pragma unroll
        for (int nt = 0; nt < 8; nt++) {
            Oa[nt][0] *= corr0; Oa[nt][1] *= corr0;
            Oa[nt][2] *= corr1; Oa[nt][3] *= corr1;
        }

        // ---- O += P V ----
#pragma unroll
        for (int ks = 0; ks < 4; ks++) {
            const int kb = ks * 16;
#pragma unroll
            for (int pr = 0; pr < 4; pr++) {
                const uint32_t bd = (uint32_t)((foffL + pr * 16 * FLDS + kb) * 2);
                uint32_t vh[4], vl[4];
                ldm_x4(vh, base + (uint32_t)(2 * F_CH * 2) + bd);
                ldm_x4(vl, base + (uint32_t)(3 * F_CH * 2) + bd);
#pragma unroll
                for (int t2 = 0; t2 < 2; t2++) {
                    const int nt = pr * 2 + t2;
                    mma16816(Oa[nt], Ph[ks][0], Ph[ks][1], Ph[ks][2], Ph[ks][3],
                             vh[t2 * 2], vh[t2 * 2 + 1]);
                    mma16816(Oa[nt], Ph[ks][0], Ph[ks][1], Ph[ks][2], Ph[ks][3],
                             vl[t2 * 2], vl[t2 * 2 + 1]);
                    mma16816(Oa[nt], Pl[ks][0], Pl[ks][1], Pl[ks][2], Pl[ks][3],
                             vh[t2 * 2], vh[t2 * 2 + 1]);
                }
            }
        }

        if (more) f_sts(fsm + (par ^ 1) * F_BUF, lr, lc0, rg);
    }

    // ---- epilogue: write split fp16 attention output ----
    const float inv0 = 1.f / l0, inv1 = 1.f / l1;
    const int row0 = q0 + w * 16 + gid;
#pragma unroll
    for (int nt = 0; nt < 8; nt++) {
        const int col = h * 64 + nt * 8 + tig * 2;
        const float o00 = Oa[nt][0] * inv0, o01 = Oa[nt][1] * inv0;
        const float o10 = Oa[nt][2] * inv1, o11 = Oa[nt][3] * inv1;
        __half h00 = __float2half_rn(o00), h01 = __float2half_rn(o01);
        __half h10 = __float2half_rn(o10), h11 = __float2half_rn(o11);
        const size_t i0 = ((size_t)b * SQL + row0) * 1024 + col;
        const size_t i1 = ((size_t)b * SQL + row0 + 8) * 1024 + col;
        *(uint32_t*)&g_AOhi[i0] = pack_h2(__half2float(h00), __half2float(h01));
        *(uint32_t*)&g_AOhi[i1] = pack_h2(__half2float(h10), __half2float(h11));
        *(uint32_t*)&g_AOlo[i0] = pack_h2(o00 - __half2float(h00), o01 - __half2float(h01));
        *(uint32_t*)&g_AOlo[i1] = pack_h2(o10 - __half2float(h10), o11 - __half2float(h11));
    }
}

// ---------------------------------------------------------------------------
extern "C" void kernel_launch(void* const* d_in, const int* in_sizes, int n_in,
                              void* d_out, int out_size)
{
    const float* query = (const float*)d_in[0];
    const float* key   = (const float*)d_in[1];
    const float* value = (const float*)d_in[2];
    const int*   kpm   = (const int*)  d_in[3];
    const float* Wq    = (const float*)d_in[4];
    const float* bq    = (const float*)d_in[5];
    const float* Wk    = (const float*)d_in[6];
    const float* bk    = (const float*)d_in[7];
    const float* Wv    = (const float*)d_in[8];
    const float* bv    = (const float*)d_in[9];
    const float* Wo    = (const float*)d_in[10];
    const float* bo    = (const float*)d_in[11];
    float* out = (float*)d_out;

    __half *qsh, *qsl, *ksh, *ksl, *vsh, *vsl;
    __half *wqh, *wql, *wkh, *wkl, *wvh, *wvl, *woh, *wol;
    cudaGetSymbolAddress((void**)&qsh, g_qsh);
    cudaGetSymbolAddress((void**)&qsl, g_qsl);
    cudaGetSymbolAddress((void**)&ksh, g_ksh);
    cudaGetSymbolAddress((void**)&ksl, g_ksl);
    cudaGetSymbolAddress((void**)&vsh, g_vsh);
    cudaGetSymbolAddress((void**)&vsl, g_vsl);
    cudaGetSymbolAddress((void**)&wqh, g_wqh);
    cudaGetSymbolAddress((void**)&wql, g_wql);
    cudaGetSymbolAddress((void**)&wkh, g_wkh);
    cudaGetSymbolAddress((void**)&wkl, g_wkl);
    cudaGetSymbolAddress((void**)&wvh, g_wvh);
    cudaGetSymbolAddress((void**)&wvl, g_wvl);
    cudaGetSymbolAddress((void**)&woh, g_woh);
    cudaGetSymbolAddress((void**)&wol, g_wol);

    cudaFuncSetAttribute(qkv_gemm, cudaFuncAttributeMaxDynamicSharedMemorySize,
                         G_SMEM);
    cudaFuncSetAttribute(o_gemm, cudaFuncAttributeMaxDynamicSharedMemorySize,
                         G_SMEM);
    cudaFuncSetAttribute(flash_tc, cudaFuncAttributeMaxDynamicSharedMemorySize,
                         F_SMEM);

    scan_mask<<<BB, 256>>>(kpm);

    const int gin = (int)(NIN / 1024);
    const int gw  = (int)(NW  / 1024);
    split_src<<<gin, 256>>>(query, qsh, qsl);
    split_src<<<gin, 256>>>(key,   ksh, ksl);
    split_src<<<gin, 256>>>(value, vsh, vsl);
    split_src<<<gw, 256>>>(Wq, wqh, wql);
    split_src<<<gw, 256>>>(Wk, wkh, wkl);
    split_src<<<gw, 256>>>(Wv, wvh, wvl);
    split_src<<<gw, 256>>>(Wo, woh, wol);

    dim3 gQKV(DMODEL / 128, (BB * SQL) / 128, 3);   // (8, 64, 3)
    qkv_gemm<<<gQKV, 256, G_SMEM>>>(bq, bk, bv);

    prep_vt<<<dim3(SKL / 64, NH, BB), 256>>>();

    flash_tc<<<dim3(SQL / 128, NH, BB), 256, F_SMEM>>>();

    dim3 gO(DMODEL / 128, (BB * SQL) / 128);        // (8, 64)
    o_gemm<<<gO, 256, G_SMEM>>>(bo, out);
}

// round 8
// speedup vs baseline: 7.2764x; 1.2456x over previous
#include <cuda_runtime.h>
#include <cuda_fp16.h>
#include <cstdint>

#define BB     4
#define SQL    2048
#define SKL    2048
#define DMODEL 1024
#define NH     16
#define HDIM   64
#define NKMAX  2048

#define NIN  ((size_t)BB * SQL * DMODEL)
#define NW   ((size_t)DMODEL * DMODEL)

// Pre-converted sources
__device__ __half g_qsh[NIN];               // fp16 single (QK path)
__device__ __half g_ksh[NIN];
__device__ __half g_vsh[NIN], g_vsl[NIN];   // split (V path)
__device__ __half g_wqh[NW];
__device__ __half g_wkh[NW];
__device__ __half g_wvh[NW],  g_wvl[NW];
__device__ __half g_woh[NW],  g_wol[NW];
// Projected tensors
__device__ __half g_Qhi[NIN];               // Q single fp16 (scale folded)
__device__ __half g_Khi[NIN];               // K compacted single fp16
__device__ float  g_Vc [NIN];               // V compacted f32
__device__ __half g_Vthi[(size_t)BB * NH * HDIM * NKMAX];
__device__ __half g_Vtlo[(size_t)BB * NH * HDIM * NKMAX];
__device__ __half g_AOhi[NIN], g_AOlo[NIN]; // attention out split
__device__ int g_rowmap[BB * SKL];
__device__ int g_knum[BB];

// ===========================================================================
// PTX helpers
// ===========================================================================
__device__ __forceinline__ void mma16816(float c[4],
                                         uint32_t a0, uint32_t a1,
                                         uint32_t a2, uint32_t a3,
                                         uint32_t b0, uint32_t b1) {
    asm volatile(
        "mma.sync.aligned.m16n8k16.row.col.f32.f16.f16.f32 "
        "{%0,%1,%2,%3}, {%4,%5,%6,%7}, {%8,%9}, {%0,%1,%2,%3};"
        : "+f"(c[0]), "+f"(c[1]), "+f"(c[2]), "+f"(c[3])
        : "r"(a0), "r"(a1), "r"(a2), "r"(a3), "r"(b0), "r"(b1));
}

__device__ __forceinline__ void ldm_x4(uint32_t* r, uint32_t saddr) {
    asm volatile(
        "ldmatrix.sync.aligned.m8n8.x4.shared.b16 {%0,%1,%2,%3}, [%4];"
        : "=r"(r[0]), "=r"(r[1]), "=r"(r[2]), "=r"(r[3]) : "r"(saddr));
}

__device__ __forceinline__ uint32_t s2u(const void* p) {
    return (uint32_t)__cvta_generic_to_shared(p);
}

__device__ __forceinline__ uint32_t pack_h2(float a, float b) {
    __half2 h = __floats2half2_rn(a, b);
    return *(uint32_t*)&h;
}

__device__ __forceinline__ void split_pack4(float4 v, uint2& h, uint2& l) {
    __half hx = __float2half_rn(v.x);
    __half hy = __float2half_rn(v.y);
    __half hz = __float2half_rn(v.z);
    __half hw = __float2half_rn(v.w);
    h.x = pack_h2(__half2float(hx), __half2float(hy));
    h.y = pack_h2(__half2float(hz), __half2float(hw));
    l.x = pack_h2(v.x - __half2float(hx), v.y - __half2float(hy));
    l.y = pack_h2(v.z - __half2float(hz), v.w - __half2float(hw));
}

// ===========================================================================
// Preps
// ===========================================================================
__global__ __launch_bounds__(256) void split_src(
    const float* __restrict__ src, __half* __restrict__ hi,
    __half* __restrict__ lo)
{
    const size_t i = (size_t)blockIdx.x * 256 + threadIdx.x;
    float4 v = *(const float4*)(src + i * 4);
    uint2 h, l;
    split_pack4(v, h, l);
    *(uint2*)(hi + i * 4) = h;
    *(uint2*)(lo + i * 4) = l;
}

__global__ __launch_bounds__(256) void cvt_src(
    const float* __restrict__ src, __half* __restrict__ hi)
{
    const size_t i = (size_t)blockIdx.x * 256 + threadIdx.x;
    float4 v = *(const float4*)(src + i * 4);
    uint2 h;
    h.x = pack_h2(v.x, v.y);
    h.y = pack_h2(v.z, v.w);
    *(uint2*)(hi + i * 4) = h;
}

__global__ __launch_bounds__(256) void scan_mask(const int* __restrict__ kpm) {
    const int b = blockIdx.x, t = threadIdx.x;
    __shared__ int cnt[256];
    int loc[8], c = 0;
#pragma unroll
    for (int i = 0; i < 8; i++) {
        loc[i] = (kpm[b * SKL + t * 8 + i] != 0) ? 1 : 0;
        c += loc[i];
    }
    cnt[t] = c;
    __syncthreads();
    for (int off = 1; off < 256; off <<= 1) {
        int v = (t >= off) ? cnt[t - off] : 0;
        __syncthreads();
        cnt[t] += v;
        __syncthreads();
    }
    int pos = cnt[t] - c;
#pragma unroll
    for (int i = 0; i < 8; i++) g_rowmap[b * SKL + t * 8 + i] = -1;
    __syncthreads();
#pragma unroll
    for (int i = 0; i < 8; i++) {
        if (loc[i]) g_rowmap[b * SKL + pos++] = b * SKL + t * 8 + i;
    }
    if (t == 255) g_knum[b] = cnt[255];
}

// ===========================================================================
// GEMM body, templated on number of split terms NT (1 or 3).
// C[M,1024] = gather(A)[M,1024] @ W^T + bias.
// ===========================================================================
#define LDSROW 40
#define G_ARR  (128 * LDSROW)

template<int NT>
__device__ __forceinline__ void g_ldg(
    const __half* Ah, const __half* Al,
    const __half* Wh, const __half* Wl,
    bool av, size_t aoff, size_t boff, int k0, uint4* rg)
{
    if (av) {
        rg[0] = *(const uint4*)(Ah + aoff + k0);
        rg[1] = *(const uint4*)(Ah + aoff + k0 + 8);
        if (NT == 3) {
            rg[2] = *(const uint4*)(Al + aoff + k0);
            rg[3] = *(const uint4*)(Al + aoff + k0 + 8);
        }
    } else {
        rg[0] = rg[1] = make_uint4(0u, 0u, 0u, 0u);
        if (NT == 3) rg[2] = rg[3] = make_uint4(0u, 0u, 0u, 0u);
    }
    rg[4] = *(const uint4*)(Wh + boff + k0);
    rg[5] = *(const uint4*)(Wh + boff + k0 + 8);
    if (NT == 3) {
        rg[6] = *(const uint4*)(Wl + boff + k0);
        rg[7] = *(const uint4*)(Wl + boff + k0 + 8);
    }
}

template<int NT>
__device__ __forceinline__ void g_sts(__half* buf, int lrow, int lcol,
                                      const uint4* rg)
{
    const int BHI = (NT == 1) ? G_ARR : 2 * G_ARR;
    const int o = lrow * LDSROW + lcol;
    *(uint4*)&buf[o]           = rg[0];
    *(uint4*)&buf[o + 8]       = rg[1];
    if (NT == 3) {
        *(uint4*)&buf[G_ARR + o]     = rg[2];
        *(uint4*)&buf[G_ARR + o + 8] = rg[3];
    }
    *(uint4*)&buf[BHI + o]     = rg[4];
    *(uint4*)&buf[BHI + o + 8] = rg[5];
    if (NT == 3) {
        *(uint4*)&buf[3 * G_ARR + o]     = rg[6];
        *(uint4*)&buf[3 * G_ARR + o + 8] = rg[7];
    }
}

template<int NT>
__device__ __forceinline__ void gemm_body(
    const __half* __restrict__ Ah, const __half* __restrict__ Al,
    const __half* __restrict__ Wh, const __half* __restrict__ Wl,
    const float* __restrict__ bias,
    float* __restrict__ Cf, __half* __restrict__ Chi, __half* __restrict__ Clo,
    float oscale, const int* __restrict__ rowmap, __half* gsm)
{
    const int BUFSZ = (NT == 1 ? 2 : 4) * G_ARR;
    const int BHI   = (NT == 1) ? G_ARR : 2 * G_ARR;

    const int tid  = threadIdx.x;
    const int w    = tid >> 5;
    const int lane = tid & 31;
    const int gid  = lane >> 2;
    const int tig  = lane & 3;
    const int bm   = blockIdx.y * 128;
    const int bn   = blockIdx.x * 128;
    const int wm = (w & 1) * 64;
    const int wn = (w >> 1) * 32;

    float acc[4][4][4];
#pragma unroll
    for (int i = 0; i < 4; i++)
#pragma unroll
        for (int j = 0; j < 4; j++)
#pragma unroll
            for (int k = 0; k < 4; k++) acc[i][j][k] = 0.f;

    const int lrow = tid >> 1;
    const int lcol = (tid & 1) * 16;
    int srow = bm + lrow;
    if (rowmap) srow = rowmap[srow];
    const bool avalid = (srow >= 0);
    const size_t aoff = (size_t)(avalid ? srow : 0) * 1024 + lcol;
    const size_t boff = (size_t)(bn + lrow) * 1024 + lcol;

    const uint32_t sb = s2u(gsm);
    const int aoffL = (wm + (lane & 15)) * LDSROW + (lane >> 4) * 8;
    const int boffL = (wn + ((lane & 7) | ((lane >> 1) & 8))) * LDSROW
                      + ((lane >> 3) & 1) * 8;

    uint4 rg[8];
    g_ldg<NT>(Ah, Al, Wh, Wl, avalid, aoff, boff, 0, rg);
    g_sts<NT>(gsm, lrow, lcol, rg);

    for (int s = 0; s < 32; s++) {
        __syncthreads();
        if (s < 31) g_ldg<NT>(Ah, Al, Wh, Wl, avalid, aoff, boff,
                              (s + 1) * 32, rg);

        const uint32_t base = sb + ((s & 1) ? (uint32_t)(BUFSZ * 2) : 0u);

#pragma unroll
        for (int ks = 0; ks < 2; ks++) {
            const int kb = ks * 16;
            uint32_t Ahi[4][4], Alo[4][4];
#pragma unroll
            for (int am = 0; am < 4; am++) {
                const uint32_t ad = (uint32_t)((aoffL + am * 16 * LDSROW + kb) * 2);
                ldm_x4(Ahi[am], base + ad);
                if (NT == 3) ldm_x4(Alo[am], base + (uint32_t)(G_ARR * 2) + ad);
            }
            uint32_t Bh[8], Bl[8];
#pragma unroll
            for (int pr = 0; pr < 2; pr++) {
                const uint32_t bd = (uint32_t)((boffL + pr * 16 * LDSROW + kb) * 2);
                ldm_x4(&Bh[pr * 4], base + (uint32_t)(BHI * 2) + bd);
                if (NT == 3)
                    ldm_x4(&Bl[pr * 4], base + (uint32_t)(3 * G_ARR * 2) + bd);
            }
#pragma unroll
            for (int am = 0; am < 4; am++)
#pragma unroll
                for (int an = 0; an < 4; an++) {
                    mma16816(acc[am][an],
                             Ahi[am][0], Ahi[am][1], Ahi[am][2], Ahi[am][3],
                             Bh[an * 2], Bh[an * 2 + 1]);
                    if (NT == 3) {
                        mma16816(acc[am][an],
                                 Ahi[am][0], Ahi[am][1], Ahi[am][2], Ahi[am][3],
                                 Bl[an * 2], Bl[an * 2 + 1]);
                        mma16816(acc[am][an],
                                 Alo[am][0], Alo[am][1], Alo[am][2], Alo[am][3],
                                 Bh[an * 2], Bh[an * 2 + 1]);
                    }
                }
        }
        if (s < 31) g_sts<NT>(gsm + ((s + 1) & 1) * BUFSZ, lrow, lcol, rg);
    }

    // Epilogue
#pragma unroll
    for (int am = 0; am < 4; am++) {
        const int row = bm + wm + am * 16 + gid;
        bool v0 = true, v1 = true;
        if (rowmap) {
            v0 = (rowmap[row] >= 0);
            v1 = (rowmap[row + 8] >= 0);
        }
#pragma unroll
        for (int an = 0; an < 4; an++) {
            const int col = bn + wn + an * 8 + tig * 2;
            const float b0 = bias[col], b1 = bias[col + 1];
            float o00 = v0 ? (acc[am][an][0] + b0) * oscale : 0.f;
            float o01 = v0 ? (acc[am][an][1] + b1) * oscale : 0.f;
            float o10 = v1 ? (acc[am][an][2] + b0) * oscale : 0.f;
            float o11 = v1 ? (acc[am][an][3] + b1) * oscale : 0.f;
            if (Chi && Clo) {
                __half h00 = __float2half_rn(o00), h01 = __float2half_rn(o01);
                __half h10 = __float2half_rn(o10), h11 = __float2half_rn(o11);
                *(uint32_t*)&Chi[(size_t)row * 1024 + col] =
                    pack_h2(__half2float(h00), __half2float(h01));
                *(uint32_t*)&Chi[(size_t)(row + 8) * 1024 + col] =
                    pack_h2(__half2float(h10), __half2float(h11));
                *(uint32_t*)&Clo[(size_t)row * 1024 + col] =
                    pack_h2(o00 - __half2float(h00), o01 - __half2float(h01));
                *(uint32_t*)&Clo[(size_t)(row + 8) * 1024 + col] =
                    pack_h2(o10 - __half2float(h10), o11 - __half2float(h11));
            } else if (Chi) {
                *(uint32_t*)&Chi[(size_t)row * 1024 + col] = pack_h2(o00, o01);
                *(uint32_t*)&Chi[(size_t)(row + 8) * 1024 + col] = pack_h2(o10, o11);
            } else {
                float2 f0 = {o00, o01}, f1 = {o10, o11};
                *(float2*)(Cf + (size_t)row * 1024 + col) = f0;
                *(float2*)(Cf + (size_t)(row + 8) * 1024 + col) = f1;
            }
        }
    }
}

#define G1_SMEM (2 * 2 * G_ARR * 2)   // 40960
#define G3_SMEM (2 * 4 * G_ARR * 2)   // 81920

// Q and K projections: single-term fp16 (softmax forgives score error)
__global__ __launch_bounds__(256) void qk_gemm(
    const float* __restrict__ bq, const float* __restrict__ bk)
{
    extern __shared__ __half gsm[];
    if (blockIdx.z == 0) {
        gemm_body<1>(g_qsh, nullptr, g_wqh, nullptr, bq,
                     nullptr, g_Qhi, nullptr, 0.125f, nullptr, gsm);
    } else {
        gemm_body<1>(g_ksh, nullptr, g_wkh, nullptr, bk,
                     nullptr, g_Khi, nullptr, 1.0f, g_rowmap, gsm);
    }
}

// V projection: 3-term, gathered, f32 out
__global__ __launch_bounds__(256) void v_gemm(const float* __restrict__ bv)
{
    extern __shared__ __half gsm[];
    gemm_body<3>(g_vsh, g_vsl, g_wvh, g_wvl, bv,
                 g_Vc, nullptr, nullptr, 1.0f, g_rowmap, gsm);
}

// O projection: 3-term, f32 out
__global__ __launch_bounds__(256) void o_gemm(
    const float* __restrict__ bo, float* __restrict__ out)
{
    extern __shared__ __half gsm[];
    gemm_body<3>(g_AOhi, g_AOlo, g_woh, g_wol, bo,
                 out, nullptr, nullptr, 1.0f, nullptr, gsm);
}

// ===========================================================================
// Prep: V transpose + split -> Vt[b][h][d][key]
// ===========================================================================
__global__ __launch_bounds__(256) void prep_vt() {
    const int b = blockIdx.z, h = blockIdx.y, j0 = blockIdx.x * 64;
    const int nv  = g_knum[b];
    const int nkp = (nv + 63) & ~63;
    if (j0 >= nkp) return;
    __shared__ float tile[64][65];
    const int t = threadIdx.x;
#pragma unroll
    for (int p = 0; p < 4; p++) {
        const int r = p * 16 + (t >> 4);
        const int c = (t & 15) * 4;
        float4 v = *(const float4*)&g_Vc[((size_t)b * SKL + j0 + r) * 1024 + h * 64 + c];
        tile[c + 0][r] = v.x; tile[c + 1][r] = v.y;
        tile[c + 2][r] = v.z; tile[c + 3][r] = v.w;
    }
    __syncthreads();
    const int d = t >> 2, jg = (t & 3) * 16;
    ushort hi[16], lo[16];
#pragma unroll
    for (int i = 0; i < 16; i++) {
        float v = tile[d][jg + i];
        __half hb = __float2half_rn(v);
        __half lb = __float2half_rn(v - __half2float(hb));
        hi[i] = *(ushort*)&hb;
        lo[i] = *(ushort*)&lb;
    }
    const size_t base = (((size_t)(b * NH + h)) * 64 + d) * NKMAX + j0 + jg;
    *(uint4*)&g_Vthi[base]     = *(uint4*)hi;
    *(uint4*)&g_Vtlo[base]     = *(uint4*)lo;
    *(uint4*)&g_Vthi[base + 8] = *(uint4*)&hi[8];
    *(uint4*)&g_Vtlo[base + 8] = *(uint4*)&lo[8];
}

// ===========================================================================
// Flash attention: single-fp16 S GEMM, 3-term PV. Double-buffered.
// ===========================================================================
#define FLDS   72
#define F_CH   (64 * FLDS)
#define F_BUF3 (3 * F_CH)
#define F_SMEM (2 * F_BUF3 * 2)   // 55296 bytes

__device__ __forceinline__ void f_ldg(int b, int h, int kt, int r, int c0,
                                      uint4* rg) {
    const size_t kb = ((size_t)b * SKL + kt + r) * 1024 + h * 64 + c0;
    rg[0] = *(const uint4*)&g_Khi[kb];
    rg[1] = *(const uint4*)&g_Khi[kb + 8];
    const size_t vb = (((size_t)(b * NH + h)) * 64 + r) * NKMAX + kt + c0;
    rg[2] = *(const uint4*)&g_Vthi[vb];
    rg[3] = *(const uint4*)&g_Vthi[vb + 8];
    rg[4] = *(const uint4*)&g_Vtlo[vb];
    rg[5] = *(const uint4*)&g_Vtlo[vb + 8];
}

__device__ __forceinline__ void f_sts(__half* buf, int r, int c0,
                                      const uint4* rg) {
    const int o = r * FLDS + c0;
    *(uint4*)&buf[o]                = rg[0];
    *(uint4*)&buf[o + 8]            = rg[1];
    *(uint4*)&buf[F_CH + o]         = rg[2];
    *(uint4*)&buf[F_CH + o + 8]     = rg[3];
    *(uint4*)&buf[2 * F_CH + o]     = rg[4];
    *(uint4*)&buf[2 * F_CH + o + 8] = rg[5];
}

__global__ __launch_bounds__(256) void flash_tc() {
    extern __shared__ __half fsm[];

    const int b = blockIdx.z, h = blockIdx.y, q0 = blockIdx.x * 128;
    const int tid = threadIdx.x;
    const int w = tid >> 5, lane = tid & 31;
    const int gid = lane >> 2, tig = lane & 3;

    const int nv  = g_knum[b];
    const int nkp = (nv + 63) & ~63;

    // ---- Stage Q (single fp16) through buffer 0, pull fragments ----
    {
        const int r = tid >> 1, c0 = (tid & 1) * 32;
        const size_t gbase = ((size_t)b * SQL + q0 + r) * 1024 + h * 64 + c0;
        __half* qh = fsm + r * FLDS + c0;
#pragma unroll
        for (int u = 0; u < 4; u++)
            *(uint4*)&qh[u * 8] = *(const uint4*)&g_Qhi[gbase + u * 8];
    }
    __syncthreads();

    const uint32_t fb = s2u(fsm);
    uint32_t Qh[4][4];
    {
        const int qoffL = (w * 16 + (lane & 15)) * FLDS + (lane >> 4) * 8;
#pragma unroll
        for (int ks = 0; ks < 4; ks++)
            ldm_x4(Qh[ks], fb + (uint32_t)((qoffL + ks * 16) * 2));
    }
    __syncthreads();

    float Oa[8][4];
#pragma unroll
    for (int i = 0; i < 8; i++)
#pragma unroll
        for (int j = 0; j < 4; j++) Oa[i][j] = 0.f;
    float m0 = -1e30f, m1 = -1e30f, l0 = 0.f, l1 = 0.f;

    const int lr = tid >> 2, lc0 = (tid & 3) * 16;
    const int foffL = ((lane & 7) | ((lane >> 1) & 8)) * FLDS
                      + ((lane >> 3) & 1) * 8;
    uint4 rg[6];
    f_ldg(b, h, 0, lr, lc0, rg);
    f_sts(fsm, lr, lc0, rg);

    int par = 0;
    for (int kt = 0; kt < nkp; kt += 64, par ^= 1) {
        __syncthreads();
        const bool more = (kt + 64) < nkp;
        if (more) f_ldg(b, h, kt + 64, lr, lc0, rg);

        const uint32_t base = fb + (uint32_t)(par * F_BUF3 * 2);

        // ---- S = Q K^T (single term) ----
        float S[8][4];
#pragma unroll
        for (int i = 0; i < 8; i++)
#pragma unroll
            for (int j = 0; j < 4; j++) S[i][j] = 0.f;

#pragma unroll
        for (int ks = 0; ks < 4; ks++) {
            const int kb = ks * 16;
#pragma unroll
            for (int pr = 0; pr < 4; pr++) {
                uint32_t kh[4];
                ldm_x4(kh, base + (uint32_t)((foffL + pr * 16 * FLDS + kb) * 2));
#pragma unroll
                for (int t2 = 0; t2 < 2; t2++) {
                    mma16816(S[pr * 2 + t2],
                             Qh[ks][0], Qh[ks][1], Qh[ks][2], Qh[ks][3],
                             kh[t2 * 2], kh[t2 * 2 + 1]);
                }
            }
        }

        // ---- tail mask ----
        if (kt + 64 > nv) {
#pragma unroll
            for (int nt = 0; nt < 8; nt++) {
                const int col = kt + nt * 8 + tig * 2;
                if (col >= nv)     { S[nt][0] = -1e30f; S[nt][2] = -1e30f; }
                if (col + 1 >= nv) { S[nt][1] = -1e30f; S[nt][3] = -1e30f; }
            }
        }

        // ---- online softmax ----
        float mx0 = -1e30f, mx1 = -1e30f;
#pragma unroll
        for (int nt = 0; nt < 8; nt++) {
            mx0 = fmaxf(mx0, fmaxf(S[nt][0], S[nt][1]));
            mx1 = fmaxf(mx1, fmaxf(S[nt][2], S[nt][3]));
        }
        mx0 = fmaxf(mx0, __shfl_xor_sync(0xffffffffu, mx0, 1));
        mx0 = fmaxf(mx0, __shfl_xor_sync(0xffffffffu, mx0, 2));
        mx1 = fmaxf(mx1, __shfl_xor_sync(0xffffffffu, mx1, 1));
        mx1 = fmaxf(mx1, __shfl_xor_sync(0xffffffffu, mx1, 2));

        const float mn0 = fmaxf(m0, mx0), mn1 = fmaxf(m1, mx1);
        const float corr0 = __expf(m0 - mn0), corr1 = __expf(m1 - mn1);
        m0 = mn0; m1 = mn1;

        float sum0 = 0.f, sum1 = 0.f;
        uint32_t Ph[4][4], Pl[4][4];
#pragma unroll
        for (int nt = 0; nt < 8; nt++) {
            const float p0 = __expf(S[nt][0] - m0);
            const float p1 = __expf(S[nt][1] - m0);
            const float p2 = __expf(S[nt][2] - m1);
            const float p3 = __expf(S[nt][3] - m1);
            sum0 += p0 + p1; sum1 += p2 + p3;
            __half h0 = __float2half_rn(p0), h1 = __float2half_rn(p1);
            __half h2 = __float2half_rn(p2), h3 = __float2half_rn(p3);
            const float f0 = __half2float(h0), f1 = __half2float(h1);
            const float f2 = __half2float(h2), f3 = __half2float(h3);
            const uint32_t hi01 = pack_h2(f0, f1);
            const uint32_t hi23 = pack_h2(f2, f3);
            const uint32_t lo01 = pack_h2(p0 - f0, p1 - f1);
            const uint32_t lo23 = pack_h2(p2 - f2, p3 - f3);
            const int ks = nt >> 1;
            if ((nt & 1) == 0) {
                Ph[ks][0] = hi01; Ph[ks][1] = hi23;
                Pl[ks][0] = lo01; Pl[ks][1] = lo23;
            } else {
                Ph[ks][2] = hi01; Ph[ks][3] = hi23;
                Pl[ks][2] = lo01; Pl[ks][3] = lo23;
            }
        }
        sum0 += __shfl_xor_sync(0xffffffffu, sum0, 1);
        sum0 += __shfl_xor_sync(0xffffffffu, sum0, 2);
        sum1 += __shfl_xor_sync(0xffffffffu, sum1, 1);
        sum1 += __shfl_xor_sync(0xffffffffu, sum1, 2);
        l0 = l0 * corr0 + sum0;
        l1 = l1 * corr1 + sum1;

#pragma unroll
        for (int nt = 0; nt < 8; nt++) {
            Oa[nt][0] *= corr0; Oa[nt][1] *= corr0;
            Oa[nt][2] *= corr1; Oa[nt][3] *= corr1;
        }

        // ---- O += P V (3-term) ----
#pragma unroll
        for (int ks = 0; ks < 4; ks++) {
            const int kb = ks * 16;
#pragma unroll
            for (int pr = 0; pr < 4; pr++) {
                const uint32_t bd = (uint32_t)((foffL + pr * 16 * FLDS + kb) * 2);
                uint32_t vh[4], vl[4];
                ldm_x4(vh, base + (uint32_t)(F_CH * 2) + bd);
                ldm_x4(vl, base + (uint32_t)(2 * F_CH * 2) + bd);
#pragma unroll
                for (int t2 = 0; t2 < 2; t2++) {
                    const int nt = pr * 2 + t2;
                    mma16816(Oa[nt], Ph[ks][0], Ph[ks][1], Ph[ks][2], Ph[ks][3],
                             vh[t2 * 2], vh[t2 * 2 + 1]);
                    mma16816(Oa[nt], Ph[ks][0], Ph[ks][1], Ph[ks][2], Ph[ks][3],
                             vl[t2 * 2], vl[t2 * 2 + 1]);
                    mma16816(Oa[nt], Pl[ks][0], Pl[ks][1], Pl[ks][2], Pl[ks][3],
                             vh[t2 * 2], vh[t2 * 2 + 1]);
                }
            }
        }

        if (more) f_sts(fsm + (par ^ 1) * F_BUF3, lr, lc0, rg);
    }

    // ---- epilogue: write split fp16 attention output ----
    const float inv0 = 1.f / l0, inv1 = 1.f / l1;
    const int row0 = q0 + w * 16 + gid;
#pragma unroll
    for (int nt = 0; nt < 8; nt++) {
        const int col = h * 64 + nt * 8 + tig * 2;
        const float o00 = Oa[nt][0] * inv0, o01 = Oa[nt][1] * inv0;
        const float o10 = Oa[nt][2] * inv1, o11 = Oa[nt][3] * inv1;
        __half h00 = __float2half_rn(o00), h01 = __float2half_rn(o01);
        __half h10 = __float2half_rn(o10), h11 = __float2half_rn(o11);
        const size_t i0 = ((size_t)b * SQL + row0) * 1024 + col;
        const size_t i1 = ((size_t)b * SQL + row0 + 8) * 1024 + col;
        *(uint32_t*)&g_AOhi[i0] = pack_h2(__half2float(h00), __half2float(h01));
        *(uint32_t*)&g_AOhi[i1] = pack_h2(__half2float(h10), __half2float(h11));
        *(uint32_t*)&g_AOlo[i0] = pack_h2(o00 - __half2float(h00), o01 - __half2float(h01));
        *(uint32_t*)&g_AOlo[i1] = pack_h2(o10 - __half2float(h10), o11 - __half2float(h11));
    }
}

// ---------------------------------------------------------------------------
extern "C" void kernel_launch(void* const* d_in, const int* in_sizes, int n_in,
                              void* d_out, int out_size)
{
    const float* query = (const float*)d_in[0];
    const float* key   = (const float*)d_in[1];
    const float* value = (const float*)d_in[2];
    const int*   kpm   = (const int*)  d_in[3];
    const float* Wq    = (const float*)d_in[4];
    const float* bq    = (const float*)d_in[5];
    const float* Wk    = (const float*)d_in[6];
    const float* bk    = (const float*)d_in[7];
    const float* Wv    = (const float*)d_in[8];
    const float* bv    = (const float*)d_in[9];
    const float* Wo    = (const float*)d_in[10];
    const float* bo    = (const float*)d_in[11];
    float* out = (float*)d_out;

    __half *qsh, *ksh, *vsh, *vsl;
    __half *wqh, *wkh, *wvh, *wvl, *woh, *wol;
    cudaGetSymbolAddress((void**)&qsh, g_qsh);
    cudaGetSymbolAddress((void**)&ksh, g_ksh);
    cudaGetSymbolAddress((void**)&vsh, g_vsh);
    cudaGetSymbolAddress((void**)&vsl, g_vsl);
    cudaGetSymbolAddress((void**)&wqh, g_wqh);
    cudaGetSymbolAddress((void**)&wkh, g_wkh);
    cudaGetSymbolAddress((void**)&wvh, g_wvh);
    cudaGetSymbolAddress((void**)&wvl, g_wvl);
    cudaGetSymbolAddress((void**)&woh, g_woh);
    cudaGetSymbolAddress((void**)&wol, g_wol);

    cudaFuncSetAttribute(qk_gemm, cudaFuncAttributeMaxDynamicSharedMemorySize,
                         G1_SMEM);
    cudaFuncSetAttribute(v_gemm, cudaFuncAttributeMaxDynamicSharedMemorySize,
                         G3_SMEM);
    cudaFuncSetAttribute(o_gemm, cudaFuncAttributeMaxDynamicSharedMemorySize,
                         G3_SMEM);
    cudaFuncSetAttribute(flash_tc, cudaFuncAttributeMaxDynamicSharedMemorySize,
                         F_SMEM);

    scan_mask<<<BB, 256>>>(kpm);

    const int gin = (int)(NIN / 1024);
    const int gw  = (int)(NW  / 1024);
    cvt_src<<<gin, 256>>>(query, qsh);
    cvt_src<<<gin, 256>>>(key,   ksh);
    split_src<<<gin, 256>>>(value, vsh, vsl);
    cvt_src<<<gw, 256>>>(Wq, wqh);
    cvt_src<<<gw, 256>>>(Wk, wkh);
    split_src<<<gw, 256>>>(Wv, wvh, wvl);
    split_src<<<gw, 256>>>(Wo, woh, wol);

    dim3 gQK(DMODEL / 128, (BB * SQL) / 128, 2);    // (8, 64, 2)
    qk_gemm<<<gQK, 256, G1_SMEM>>>(bq, bk);

    dim3 gG(DMODEL / 128, (BB * SQL) / 128);        // (8, 64)
    v_gemm<<<gG, 256, G3_SMEM>>>(bv);

    prep_vt<<<dim3(SKL / 64, NH, BB), 256>>>();

    flash_tc<<<dim3(SQL / 128, NH, BB), 256, F_SMEM>>>();

    o_gemm<<<gG, 256, G3_SMEM>>>(bo, out);
}